// round 13
// baseline (speedup 1.0000x reference)
#include <cuda_runtime.h>
#include <cuda_fp16.h>
#include <math.h>
#include <cstdint>

#define S_LEN 2048
#define BATCH 2
#define DM    1024
#define NHEAD 16
#define DKH   64
#define DFF   4096
#define NTOK  (BATCH * S_LEN)   // 4096
#define LN_EPS 1e-6f

#define GBM 128
#define GBN 128
#define GBK 64

__device__ __forceinline__ uint32_t smem_u32(const void* p) {
    uint32_t a;
    asm("{ .reg .u64 t; cvta.to.shared.u64 t, %1; cvt.u32.u64 %0, t; }"
        : "=r"(a) : "l"(p));
    return a;
}
__device__ __forceinline__ void ldsm_x4(uint32_t addr, uint32_t& r0, uint32_t& r1,
                                        uint32_t& r2, uint32_t& r3) {
    asm volatile("ldmatrix.sync.aligned.m8n8.x4.shared.b16 {%0,%1,%2,%3}, [%4];"
                 : "=r"(r0), "=r"(r1), "=r"(r2), "=r"(r3) : "r"(addr));
}
__device__ __forceinline__ void ldsm_x4_t(uint32_t addr, uint32_t& r0, uint32_t& r1,
                                          uint32_t& r2, uint32_t& r3) {
    asm volatile("ldmatrix.sync.aligned.m8n8.x4.trans.shared.b16 {%0,%1,%2,%3}, [%4];"
                 : "=r"(r0), "=r"(r1), "=r"(r2), "=r"(r3) : "r"(addr));
}
__device__ __forceinline__ void mma_f16(float* c, uint32_t a0, uint32_t a1,
                                        uint32_t a2, uint32_t a3,
                                        uint32_t b0, uint32_t b1) {
    asm volatile(
        "mma.sync.aligned.m16n8k16.row.col.f32.f16.f16.f32 "
        "{%0,%1,%2,%3}, {%4,%5,%6,%7}, {%8,%9}, {%0,%1,%2,%3};"
        : "+f"(c[0]), "+f"(c[1]), "+f"(c[2]), "+f"(c[3])
        : "r"(a0), "r"(a1), "r"(a2), "r"(a3), "r"(b0), "r"(b1));
}
#define CP_ASYNC16(dst, src) \
    asm volatile("cp.async.cg.shared.global [%0], [%1], 16;" :: "r"(dst), "l"(src))
#define CP_COMMIT() asm volatile("cp.async.commit_group;" ::: "memory")
#define CP_WAIT0()  asm volatile("cp.async.wait_group 0;" ::: "memory")

// ---------------- scratch (device globals; no allocation) ----------------
__device__ __half g_n1h[NTOK * DM];
__device__ __half g_n1l[NTOK * DM];
__device__ __half g_qh[NTOK * DM];
__device__ __half g_kh[NTOK * DM], g_kl[NTOK * DM];
__device__ __half g_vh[NTOK * DM];
__device__ __half g_aoh[NTOK * DM];
__device__ float  g_h [NTOK * DM];
__device__ __half g_n2h[NTOK * DM];
__device__ __half g_n2l[NTOK * DM];
__device__ __half g_f1h[NTOK * DFF];
__device__ __half g_wqkvh[3 * DM * DM], g_wqkvl[3 * DM * DM];
__device__ __half g_woh[DM * DM];
__device__ __half g_w1h[DM * DFF];
__device__ __half g_w2h[DFF * DM];

// ---------------- weight transpose + fp16 (hi only) -----------------------
__global__ void __launch_bounds__(256) wsplit_kernel(
    const float* __restrict__ W, __half* __restrict__ Bh, int K, int N)
{
    __shared__ float tile[32][33];
    int n0 = blockIdx.x * 32, k0 = blockIdx.y * 32;
    int tx = threadIdx.x & 31, ty = threadIdx.x >> 5;
#pragma unroll
    for (int i = 0; i < 4; i++)
        tile[ty + 8 * i][tx] = W[(size_t)(k0 + ty + 8 * i) * N + n0 + tx];
    __syncthreads();
#pragma unroll
    for (int i = 0; i < 4; i++) {
        int nl = ty + 8 * i;
        Bh[(size_t)(n0 + nl) * K + k0 + tx] = __float2half_rn(tile[tx][nl]);
    }
}

// 4 square 1024x1024 weights (lo only for the K section: z==1)
__global__ void __launch_bounds__(256) wsplit4_kernel(
    const float* __restrict__ Wq, const float* __restrict__ Wk,
    const float* __restrict__ Wv, const float* __restrict__ Wo,
    __half* __restrict__ qkvh, __half* __restrict__ qkvl,
    __half* __restrict__ woh)
{
    __shared__ float tile[32][33];
    int z = blockIdx.z;
    const float* W = (z == 0) ? Wq : (z == 1) ? Wk : (z == 2) ? Wv : Wo;
    __half* Bh = (z < 3) ? (qkvh + (size_t)z * DM * DM) : woh;
    __half* Bl = (z < 3) ? (qkvl + (size_t)z * DM * DM) : nullptr;
    int n0 = blockIdx.x * 32, k0 = blockIdx.y * 32;
    int tx = threadIdx.x & 31, ty = threadIdx.x >> 5;
#pragma unroll
    for (int i = 0; i < 4; i++)
        tile[ty + 8 * i][tx] = W[(size_t)(k0 + ty + 8 * i) * DM + n0 + tx];
    __syncthreads();
#pragma unroll
    for (int i = 0; i < 4; i++) {
        int nl = ty + 8 * i;
        float w = tile[tx][nl];
        __half h = __float2half_rn(w);
        size_t o = (size_t)(n0 + nl) * DM + k0 + tx;
        Bh[o] = h;
        if (z < 3) {
            __half l = __float2half_rn(w - __half2float(h));
            Bl[o] = l;
        }
    }
}

// ---------------- LayerNorm -> fp16 hi/lo ---------------------------------
__global__ void __launch_bounds__(256) ln_kernel(
    const float* __restrict__ x, const float* __restrict__ alpha,
    const float* __restrict__ beta, __half* __restrict__ yh,
    __half* __restrict__ yl)
{
    int row = blockIdx.x;
    int tid = threadIdx.x;
    const float4* x4 = (const float4*)(x + (size_t)row * DM);
    float4 v = x4[tid];
    float s = v.x + v.y + v.z + v.w;
    float q = v.x * v.x + v.y * v.y + v.z * v.z + v.w * v.w;

    __shared__ float rs[8], rq[8];
#pragma unroll
    for (int o = 16; o; o >>= 1) {
        s += __shfl_xor_sync(0xffffffffu, s, o);
        q += __shfl_xor_sync(0xffffffffu, q, o);
    }
    if ((tid & 31) == 0) { rs[tid >> 5] = s; rq[tid >> 5] = q; }
    __syncthreads();
    s = 0.f; q = 0.f;
#pragma unroll
    for (int i = 0; i < 8; i++) { s += rs[i]; q += rq[i]; }

    float mean = s * (1.0f / DM);
    float var  = (q - (float)DM * mean * mean) * (1.0f / (DM - 1));
    float a    = alpha[0];
    float b    = beta[0];
    float inv  = a / (sqrtf(var) + LN_EPS);

    float o0 = (v.x - mean) * inv + b;
    float o1 = (v.y - mean) * inv + b;
    float o2 = (v.z - mean) * inv + b;
    float o3 = (v.w - mean) * inv + b;

    __half2 h0 = __floats2half2_rn(o0, o1);
    __half2 h1 = __floats2half2_rn(o2, o3);
    float2 hf0 = __half22float2(h0), hf1 = __half22float2(h1);
    __half2 l0 = __floats2half2_rn(o0 - hf0.x, o1 - hf0.y);
    __half2 l1 = __floats2half2_rn(o2 - hf1.x, o3 - hf1.y);

    uint2 uh, ul;
    uh.x = *(uint32_t*)&h0; uh.y = *(uint32_t*)&h1;
    ul.x = *(uint32_t*)&l0; ul.y = *(uint32_t*)&l1;
    *(uint2*)(yh + (size_t)row * DM + tid * 4) = uh;
    *(uint2*)(yl + (size_t)row * DM + tid * 4) = ul;
}

// ---------------- 1-term HMMA GEMM (Wo / FFN) -----------------------------
template<bool RELU, bool RES, int OUT>
__global__ void __launch_bounds__(256, 2) tc2_gemm(
    const __half* __restrict__ Ah, const __half* __restrict__ Bh,
    const float* __restrict__ bias, const float* __restrict__ res,
    float* __restrict__ Cf, __half* __restrict__ Ch,
    int M, int N, int K)
{
    extern __shared__ char sm[];
    constexpr uint32_t AH_OFF = 0;
    constexpr uint32_t BH_OFF = 16384u;
    constexpr uint32_t STAGE = 32768u;

    const int tid = threadIdx.x;
    const int wid = tid >> 5;
    const int lid = tid & 31;
    const int nb = blockIdx.x, mb = blockIdx.y;

    const int warp_m = (wid >> 2) * 64;
    const int warp_n = (wid & 3) * 32;

    const uint32_t smb = smem_u32(sm);

    const int a_row = warp_m + (lid & 15);
    const uint32_t a_cb = (uint32_t)((lid >> 4) * 16);
    const int b_row_off = ((lid & 16) >> 1) + (lid & 7);
    const uint32_t b_cb = (lid & 8) ? 16u : 0u;
    const uint32_t xm = (uint32_t)((lid & 7) << 4);

    float acc[4][4][4];
#pragma unroll
    for (int i = 0; i < 4; i++)
#pragma unroll
        for (int j = 0; j < 4; j++)
#pragma unroll
            for (int r = 0; r < 4; r++) acc[i][j][r] = 0.f;

    const int sj = tid & 7;
    const int sr0 = tid >> 3;
    const int niter = K / GBK;

    auto stage = [&](int kt, int buf) {
        uint32_t base = smb + (uint32_t)buf * STAGE;
#pragma unroll
        for (int i = 0; i < 4; i++) {
            int r = i * 32 + sr0;
            uint32_t sw = (uint32_t)(r * 128 + ((sj * 16) ^ ((r & 7) << 4)));
            CP_ASYNC16(base + AH_OFF + sw, Ah + (size_t)(mb * GBM + r) * K + kt * GBK + sj * 8);
            CP_ASYNC16(base + BH_OFF + sw, Bh + (size_t)(nb * GBN + r) * K + kt * GBK + sj * 8);
        }
    };

    stage(0, 0);
    CP_COMMIT();

    for (int kt = 0; kt < niter; kt++) {
        int buf = kt & 1;
        CP_WAIT0();
        __syncthreads();
        if (kt + 1 < niter) {
            stage(kt + 1, buf ^ 1);
            CP_COMMIT();
        }

        uint32_t ah_u = smb + (uint32_t)buf * STAGE + AH_OFF;
        uint32_t bh_u = smb + (uint32_t)buf * STAGE + BH_OFF;

#pragma unroll
        for (int s = 0; s < 4; s++) {
            uint32_t bhf[8];
#pragma unroll
            for (int pr = 0; pr < 2; pr++) {
                uint32_t roff = (uint32_t)(warp_n + pr * 16 + b_row_off) * 128;
                uint32_t coff = (uint32_t)(s * 32 + b_cb) ^ xm;
                ldsm_x4(bh_u + roff + coff, bhf[pr*4+0], bhf[pr*4+1], bhf[pr*4+2], bhf[pr*4+3]);
            }
#pragma unroll
            for (int mt = 0; mt < 4; mt++) {
                uint32_t roff = (uint32_t)(a_row + mt * 16) * 128;
                uint32_t coff = (uint32_t)(s * 32 + a_cb) ^ xm;
                uint32_t a0, a1, a2, a3;
                ldsm_x4(ah_u + roff + coff, a0, a1, a2, a3);
#pragma unroll
                for (int nt = 0; nt < 4; nt++) {
                    uint32_t hb0 = bhf[(nt >> 1) * 4 + (nt & 1) * 2];
                    uint32_t hb1 = bhf[(nt >> 1) * 4 + (nt & 1) * 2 + 1];
                    mma_f16(acc[mt][nt], a0, a1, a2, a3, hb0, hb1);
                }
            }
        }
        __syncthreads();
    }

    {
        int g = lid >> 2, tig = lid & 3;
        int base_row = mb * GBM + warp_m + g;
        int base_col = nb * GBN + warp_n + tig * 2;
#pragma unroll
        for (int mt = 0; mt < 4; mt++) {
#pragma unroll
            for (int nt = 0; nt < 4; nt++) {
                int col = base_col + nt * 8;
                float2 bb = *(const float2*)(bias + col);
#pragma unroll
                for (int hrow = 0; hrow < 2; hrow++) {
                    int row = base_row + mt * 16 + hrow * 8;
                    float2 o;
                    o.x = acc[mt][nt][hrow * 2 + 0] + bb.x;
                    o.y = acc[mt][nt][hrow * 2 + 1] + bb.y;
                    if (RES) {
                        float2 r2 = *(const float2*)(res + (size_t)row * N + col);
                        o.x += r2.x; o.y += r2.y;
                    }
                    if (RELU) {
                        o.x = fmaxf(o.x, 0.f);
                        o.y = fmaxf(o.y, 0.f);
                    }
                    if (OUT == 0) {
                        *(float2*)(Cf + (size_t)row * N + col) = o;
                    } else {
                        __half2 hv = __floats2half2_rn(o.x, o.y);
                        *(__half2*)(Ch + (size_t)row * N + col) = hv;
                    }
                }
            }
        }
    }
}

// ---------------- fused QKV GEMM (M64, double-buffered) --------------------
// K section (sect==1): 3-term + hi/lo output. Q/V: 2-term, fp16 output.
__global__ void __launch_bounds__(256, 2) tc_qkv_gemm(
    const __half* __restrict__ Ah, const __half* __restrict__ Al,
    const __half* __restrict__ Bh, const __half* __restrict__ Bl,
    const float* __restrict__ bq, const float* __restrict__ bk,
    const float* __restrict__ bv,
    __half* __restrict__ Qh,
    __half* __restrict__ Kh, __half* __restrict__ Kl,
    __half* __restrict__ Vh)
{
    extern __shared__ char sm[];
    constexpr uint32_t AH_OFF = 0;
    constexpr uint32_t AL_OFF = 8192u;
    constexpr uint32_t BH_OFF = 16384u;
    constexpr uint32_t BL_OFF = 32768u;
    const uint32_t STAGE = 49152u;
    const int K = DM;

    const int tid = threadIdx.x;
    const int wid = tid >> 5;
    const int lid = tid & 31;
    const int nb = blockIdx.x, mb = blockIdx.y;
    const int sect = nb >> 3;
    const bool three_term = (sect == 1);

    const int warp_m = (wid >> 2) * 32;
    const int warp_n = (wid & 3) * 32;

    const uint32_t smb = smem_u32(sm);

    const int a_row = warp_m + (lid & 15);
    const uint32_t a_cb = (uint32_t)((lid >> 4) * 16);
    const int b_row_off = ((lid & 16) >> 1) + (lid & 7);
    const uint32_t b_cb = (lid & 8) ? 16u : 0u;
    const uint32_t xm = (uint32_t)((lid & 7) << 4);

    float acc[2][4][4];
#pragma unroll
    for (int i = 0; i < 2; i++)
#pragma unroll
        for (int j = 0; j < 4; j++)
#pragma unroll
            for (int r = 0; r < 4; r++) acc[i][j][r] = 0.f;

    const int sj = tid & 7;
    const int sr0 = tid >> 3;
    const int niter = K / GBK;

    auto stage = [&](int kt, int buf) {
        uint32_t base = smb + (uint32_t)buf * STAGE;
#pragma unroll
        for (int i = 0; i < 2; i++) {
            int r = i * 32 + sr0;
            uint32_t sw = (uint32_t)(r * 128 + ((sj * 16) ^ ((r & 7) << 4)));
            CP_ASYNC16(base + AH_OFF + sw, Ah + (size_t)(mb * 64 + r) * K + kt * GBK + sj * 8);
            if (three_term)
                CP_ASYNC16(base + AL_OFF + sw, Al + (size_t)(mb * 64 + r) * K + kt * GBK + sj * 8);
        }
#pragma unroll
        for (int i = 0; i < 4; i++) {
            int r = i * 32 + sr0;
            uint32_t sw = (uint32_t)(r * 128 + ((sj * 16) ^ ((r & 7) << 4)));
            CP_ASYNC16(base + BH_OFF + sw, Bh + (size_t)(nb * GBN + r) * K + kt * GBK + sj * 8);
            CP_ASYNC16(base + BL_OFF + sw, Bl + (size_t)(nb * GBN + r) * K + kt * GBK + sj * 8);
        }
    };

    stage(0, 0);
    CP_COMMIT();

    for (int kt = 0; kt < niter; kt++) {
        int buf = kt & 1;
        CP_WAIT0();
        __syncthreads();
        if (kt + 1 < niter) {
            stage(kt + 1, buf ^ 1);
            CP_COMMIT();
        }

        uint32_t ah_u = smb + (uint32_t)buf * STAGE + AH_OFF;
        uint32_t al_u = smb + (uint32_t)buf * STAGE + AL_OFF;
        uint32_t bh_u = smb + (uint32_t)buf * STAGE + BH_OFF;
        uint32_t bl_u = smb + (uint32_t)buf * STAGE + BL_OFF;

#pragma unroll
        for (int s = 0; s < 4; s++) {
            uint32_t bhf[8], blf[8];
#pragma unroll
            for (int pr = 0; pr < 2; pr++) {
                uint32_t roff = (uint32_t)(warp_n + pr * 16 + b_row_off) * 128;
                uint32_t coff = (uint32_t)(s * 32 + b_cb) ^ xm;
                ldsm_x4(bh_u + roff + coff, bhf[pr*4+0], bhf[pr*4+1], bhf[pr*4+2], bhf[pr*4+3]);
                ldsm_x4(bl_u + roff + coff, blf[pr*4+0], blf[pr*4+1], blf[pr*4+2], blf[pr*4+3]);
            }
#pragma unroll
            for (int mt = 0; mt < 2; mt++) {
                uint32_t roff = (uint32_t)(a_row + mt * 16) * 128;
                uint32_t coff = (uint32_t)(s * 32 + a_cb) ^ xm;
                uint32_t a0, a1, a2, a3, l0, l1, l2, l3;
                ldsm_x4(ah_u + roff + coff, a0, a1, a2, a3);
                if (three_term)
                    ldsm_x4(al_u + roff + coff, l0, l1, l2, l3);
#pragma unroll
                for (int nt = 0; nt < 4; nt++) {
                    uint32_t hb0 = bhf[(nt >> 1) * 4 + (nt & 1) * 2];
                    uint32_t hb1 = bhf[(nt >> 1) * 4 + (nt & 1) * 2 + 1];
                    uint32_t lb0 = blf[(nt >> 1) * 4 + (nt & 1) * 2];
                    uint32_t lb1 = blf[(nt >> 1) * 4 + (nt & 1) * 2 + 1];
                    mma_f16(acc[mt][nt], a0, a1, a2, a3, hb0, hb1);
                    mma_f16(acc[mt][nt], a0, a1, a2, a3, lb0, lb1);
                    if (three_term)
                        mma_f16(acc[mt][nt], l0, l1, l2, l3, hb0, hb1);
                }
            }
        }
        __syncthreads();
    }

    {
        int nb_l = nb & 7;
        const float* bp = (sect == 0) ? bq : ((sect == 1) ? bk : bv);
        __half* Dh = (sect == 0) ? Qh : ((sect == 1) ? Kh : Vh);

        int g = lid >> 2, tig = lid & 3;
        int base_row = mb * 64 + warp_m + g;
        int base_col = nb_l * GBN + warp_n + tig * 2;
#pragma unroll
        for (int mt = 0; mt < 2; mt++) {
#pragma unroll
            for (int nt = 0; nt < 4; nt++) {
                int col = base_col + nt * 8;
                float2 bb = *(const float2*)(bp + col);
#pragma unroll
                for (int hrow = 0; hrow < 2; hrow++) {
                    int row = base_row + mt * 16 + hrow * 8;
                    float ox = acc[mt][nt][hrow * 2 + 0] + bb.x;
                    float oy = acc[mt][nt][hrow * 2 + 1] + bb.y;
                    __half2 hv = __floats2half2_rn(ox, oy);
                    *(__half2*)(Dh + (size_t)row * DM + col) = hv;
                    if (three_term) {
                        float2 hf = __half22float2(hv);
                        __half2 lv = __floats2half2_rn(ox - hf.x, oy - hf.y);
                        *(__half2*)(Kl + (size_t)row * DM + col) = lv;
                    }
                }
            }
        }
    }
}

// ---------------- HMMA flash attention (Q fp16, K hi/lo, 2-term QK) -------
#define AQH 0u
#define ABUF0 16384u
#define ABUFSZ 24576u
#define APB 65536u
#define ATTN_SMEM 81920

__global__ void __launch_bounds__(256, 2) fattn_mma(
    const __half* __restrict__ Qh,
    const __half* __restrict__ Kh, const __half* __restrict__ Kl,
    const __half* __restrict__ Vh, __half* __restrict__ Oh)
{
    extern __shared__ char sm[];
    const uint32_t smb = smem_u32(sm);

    const int tid = threadIdx.x;
    const int wid = tid >> 5;
    const int lid = tid & 31;
    const int h = blockIdx.y, b = blockIdx.z;
    const int q0 = blockIdx.x * 128;

    const int warp_m = wid * 16;

    const int a_row = warp_m + (lid & 15);
    const uint32_t a_cb = (uint32_t)((lid >> 4) * 16);
    const int b_row_off = ((lid & 16) >> 1) + (lid & 7);
    const uint32_t b_cb = (lid & 8) ? 16u : 0u;
    const uint32_t xm = (uint32_t)((lid & 7) << 4);

    const int v_krow = lid & 15;
    const uint32_t v_db = (uint32_t)((lid >> 4) << 4);

    const size_t bh_off = ((size_t)b * S_LEN) * DM + h * DKH;

    const int sj = tid & 7;
    const int sr0 = tid >> 3;

    {
#pragma unroll
        for (int i = 0; i < 4; i++) {
            int r = sr0 + i * 32;
            uint32_t sw = (uint32_t)(r * 128 + ((sj * 16) ^ ((r & 7) << 4)));
            CP_ASYNC16(smb + AQH + sw, Qh + bh_off + (size_t)(q0 + r) * DM + sj * 8);
        }
        CP_COMMIT();
    }

    auto stage_kv = [&](int k0, int buf) {
        uint32_t base = smb + ABUF0 + (uint32_t)buf * ABUFSZ;
#pragma unroll
        for (int i = 0; i < 2; i++) {
            int r = sr0 + i * 32;
            uint32_t sw = (uint32_t)(r * 128 + ((sj * 16) ^ ((r & 7) << 4)));
            CP_ASYNC16(base + sw,          Kh + bh_off + (size_t)(k0 + r) * DM + sj * 8);
            CP_ASYNC16(base + 8192u + sw,  Kl + bh_off + (size_t)(k0 + r) * DM + sj * 8);
            CP_ASYNC16(base + 16384u + sw, Vh + bh_off + (size_t)(k0 + r) * DM + sj * 8);
        }
    };

    stage_kv(0, 0);
    CP_COMMIT();

    float Oa[8][4];
    float mrow[2], lrow[2];
#pragma unroll
    for (int nt = 0; nt < 8; nt++)
#pragma unroll
        for (int r = 0; r < 4; r++) Oa[nt][r] = 0.f;
    mrow[0] = mrow[1] = -INFINITY;
    lrow[0] = lrow[1] = 0.f;

    CP_WAIT0();
    __syncthreads();

    const int NT = S_LEN / 64;
    for (int t = 0; t < NT; t++) {
        int buf = t & 1;
        uint32_t kh_u = smb + ABUF0 + (uint32_t)buf * ABUFSZ;
        uint32_t kl_u = kh_u + 8192u;
        uint32_t vs_u = kh_u + 16384u;

        if (t + 1 < NT) {
            stage_kv((t + 1) * 64, buf ^ 1);
            CP_COMMIT();
        }

        // ---- phase A: S = Q (Kh + Kl)^T (2-term) ----
        float sacc[8][4];
#pragma unroll
        for (int nt = 0; nt < 8; nt++)
#pragma unroll
            for (int r = 0; r < 4; r++) sacc[nt][r] = 0.f;

#pragma unroll
        for (int s = 0; s < 4; s++) {
            uint32_t acoff = (uint32_t)(s * 32 + a_cb) ^ xm;
            uint32_t qa0, qa1, qa2, qa3;
            ldsm_x4(smb + AQH + (uint32_t)a_row * 128 + acoff, qa0, qa1, qa2, qa3);
            uint32_t bcoff = (uint32_t)(s * 32 + b_cb) ^ xm;
#pragma unroll
            for (int pr = 0; pr < 4; pr++) {
                uint32_t roff = (uint32_t)(pr * 16 + b_row_off) * 128;
                uint32_t h0, h1, h2, h3, l0, l1, l2, l3;
                ldsm_x4(kh_u + roff + bcoff, h0, h1, h2, h3);
                ldsm_x4(kl_u + roff + bcoff, l0, l1, l2, l3);
                mma_f16(sacc[pr*2+0], qa0, qa1, qa2, qa3, h0, h1);
                mma_f16(sacc[pr*2+0], qa0, qa1, qa2, qa3, l0, l1);
                mma_f16(sacc[pr*2+1], qa0, qa1, qa2, qa3, h2, h3);
                mma_f16(sacc[pr*2+1], qa0, qa1, qa2, qa3, l2, l3);
            }
        }

        // ---- online softmax on fragments ----
        float corr0, corr1;
#pragma unroll
        for (int r = 0; r < 2; r++) {
            float mx = -INFINITY;
#pragma unroll
            for (int nt = 0; nt < 8; nt++) {
                mx = fmaxf(mx, sacc[nt][r*2+0]);
                mx = fmaxf(mx, sacc[nt][r*2+1]);
            }
            mx = fmaxf(mx, __shfl_xor_sync(0xffffffffu, mx, 1));
            mx = fmaxf(mx, __shfl_xor_sync(0xffffffffu, mx, 2));
            float mn = fmaxf(mrow[r], mx);
            float c = __expf(mrow[r] - mn);
            mrow[r] = mn;
            float sum = 0.f;
#pragma unroll
            for (int nt = 0; nt < 8; nt++) {
                float e0 = __expf(sacc[nt][r*2+0] - mn);
                float e1 = __expf(sacc[nt][r*2+1] - mn);
                sacc[nt][r*2+0] = e0;
                sacc[nt][r*2+1] = e1;
                sum += e0 + e1;
            }
            sum += __shfl_xor_sync(0xffffffffu, sum, 1);
            sum += __shfl_xor_sync(0xffffffffu, sum, 2);
            lrow[r] = lrow[r] * c + sum;
            if (r == 0) corr0 = c; else corr1 = c;
        }
#pragma unroll
        for (int nt = 0; nt < 8; nt++) {
            Oa[nt][0] *= corr0; Oa[nt][1] *= corr0;
            Oa[nt][2] *= corr1; Oa[nt][3] *= corr1;
        }

        // ---- store P fp16 (warp-local rows) ----
        __syncwarp();
        {
            int g = lid >> 2, tig = lid & 3;
            int row0 = warp_m + g;
            int row1 = row0 + 8;
            uint32_t x0 = (uint32_t)((row0 & 7) << 4);
            uint32_t x1 = (uint32_t)((row1 & 7) << 4);
#pragma unroll
            for (int nt = 0; nt < 8; nt++) {
                int col = tig * 2 + nt * 8;
                __half2 p0 = __floats2half2_rn(sacc[nt][0], sacc[nt][1]);
                __half2 p1 = __floats2half2_rn(sacc[nt][2], sacc[nt][3]);
                *(__half2*)(sm + APB + (uint32_t)(row0 * 128 + ((col * 2) ^ x0))) = p0;
                *(__half2*)(sm + APB + (uint32_t)(row1 * 128 + ((col * 2) ^ x1))) = p1;
            }
        }
        __syncwarp();

        // ---- phase B: O += P @ V ----
#pragma unroll
        for (int s = 0; s < 4; s++) {
            uint32_t acoff = (uint32_t)(s * 32 + a_cb) ^ xm;
            uint32_t pa0, pa1, pa2, pa3;
            ldsm_x4(smb + APB + (uint32_t)a_row * 128 + acoff, pa0, pa1, pa2, pa3);
            int krow = s * 16 + v_krow;
#pragma unroll
            for (int pr = 0; pr < 4; pr++) {
                uint32_t vaddr = vs_u + (uint32_t)krow * 128 +
                                 (((uint32_t)(pr * 32) + v_db) ^ ((uint32_t)(krow & 7) << 4));
                uint32_t v0, v1, v2, v3;
                ldsm_x4_t(vaddr, v0, v1, v2, v3);
                mma_f16(Oa[pr*2+0], pa0, pa1, pa2, pa3, v0, v1);
                mma_f16(Oa[pr*2+1], pa0, pa1, pa2, pa3, v2, v3);
            }
        }

        if (t + 1 < NT) CP_WAIT0();
        __syncthreads();
    }

    {
        int g = lid >> 2, tig = lid & 3;
        float inv0 = 1.0f / lrow[0];
        float inv1 = 1.0f / lrow[1];
        int row0 = q0 + warp_m + g;
        int row1 = row0 + 8;
#pragma unroll
        for (int nt = 0; nt < 8; nt++) {
            int col = tig * 2 + nt * 8;
            __half2 o0 = __floats2half2_rn(Oa[nt][0] * inv0, Oa[nt][1] * inv0);
            __half2 o1 = __floats2half2_rn(Oa[nt][2] * inv1, Oa[nt][3] * inv1);
            *(__half2*)(Oh + bh_off + (size_t)row0 * DM + col) = o0;
            *(__half2*)(Oh + bh_off + (size_t)row1 * DM + col) = o1;
        }
    }
}

// ---------------- launch ----------------
extern "C" void kernel_launch(void* const* d_in, const int* in_sizes, int n_in,
                              void* d_out, int out_size)
{
    const float* x    = (const float*)d_in[0];
    const float* Wq   = (const float*)d_in[1];
    const float* bq   = (const float*)d_in[2];
    const float* Wk   = (const float*)d_in[3];
    const float* bk   = (const float*)d_in[4];
    const float* Wv   = (const float*)d_in[5];
    const float* bv   = (const float*)d_in[6];
    const float* Wo   = (const float*)d_in[7];
    const float* bo   = (const float*)d_in[8];
    const float* W1   = (const float*)d_in[9];
    const float* b1   = (const float*)d_in[10];
    const float* W2   = (const float*)d_in[11];
    const float* b2   = (const float*)d_in[12];
    const float* ln1a = (const float*)d_in[13];
    const float* ln1b = (const float*)d_in[14];
    const float* ln2a = (const float*)d_in[15];
    const float* ln2b = (const float*)d_in[16];
    float* out = (float*)d_out;

    __half *p_n1h, *p_n1l, *p_qh, *p_kh, *p_kl, *p_vh;
    __half *p_aoh, *p_n2h, *p_n2l, *p_f1h;
    float *p_h;
    __half *wqkvh, *wqkvl, *woh, *w1h, *w2h;
    cudaGetSymbolAddress((void**)&p_n1h, g_n1h);
    cudaGetSymbolAddress((void**)&p_n1l, g_n1l);
    cudaGetSymbolAddress((void**)&p_qh, g_qh);
    cudaGetSymbolAddress((void**)&p_kh, g_kh);
    cudaGetSymbolAddress((void**)&p_kl, g_kl);
    cudaGetSymbolAddress((void**)&p_vh, g_vh);
    cudaGetSymbolAddress((void**)&p_aoh, g_aoh);
    cudaGetSymbolAddress((void**)&p_h,  g_h);
    cudaGetSymbolAddress((void**)&p_n2h, g_n2h);
    cudaGetSymbolAddress((void**)&p_n2l, g_n2l);
    cudaGetSymbolAddress((void**)&p_f1h, g_f1h);
    cudaGetSymbolAddress((void**)&wqkvh, g_wqkvh);
    cudaGetSymbolAddress((void**)&wqkvl, g_wqkvl);
    cudaGetSymbolAddress((void**)&woh, g_woh);
    cudaGetSymbolAddress((void**)&w1h, g_w1h);
    cudaGetSymbolAddress((void**)&w2h, g_w2h);

    const int SMEM1 = 2 * 2 * 16384;   // 64KB
    const int SMEMQ = 2 * 49152;       // 96KB

    cudaFuncSetAttribute(fattn_mma,
                         cudaFuncAttributeMaxDynamicSharedMemorySize, ATTN_SMEM);
    cudaFuncSetAttribute(tc_qkv_gemm,
                         cudaFuncAttributeMaxDynamicSharedMemorySize, SMEMQ);
    cudaFuncSetAttribute(tc2_gemm<false, true, 0>,
                         cudaFuncAttributeMaxDynamicSharedMemorySize, SMEM1);
    cudaFuncSetAttribute(tc2_gemm<true, false, 1>,
                         cudaFuncAttributeMaxDynamicSharedMemorySize, SMEM1);

    // 0) weight transpose + split (lo only for K)
    wsplit4_kernel<<<dim3(DM / 32, DM / 32, 4), 256>>>(
        Wq, Wk, Wv, Wo, wqkvh, wqkvl, woh);
    wsplit_kernel<<<dim3(DFF / 32, DM / 32), 256>>>(W1, w1h, DM, DFF);
    wsplit_kernel<<<dim3(DM / 32, DFF / 32), 256>>>(W2, w2h, DFF, DM);

    // 1) LN1 -> fp16 hi/lo
    ln_kernel<<<NTOK, 256>>>(x, ln1a, ln1b, p_n1h, p_n1l);

    // 2) fused QKV projection (K: 3-term + hi/lo; Q/V: 2-term fp16)
    tc_qkv_gemm<<<dim3(3 * DM / GBN, NTOK / 64), 256, SMEMQ>>>(
        p_n1h, p_n1l, wqkvh, wqkvl, bq, bk, bv,
        p_qh, p_kh, p_kl, p_vh);

    // 3) HMMA flash attention (2-term QK; no 1/sqrt(dk) scaling)
    fattn_mma<<<dim3(S_LEN / 128, NHEAD, BATCH), 256, ATTN_SMEM>>>(
        p_qh, p_kh, p_kl, p_vh, p_aoh);

    // 4) output projection + residual(x) -> h fp32 (1-term)
    dim3 gP(DM / GBN, NTOK / GBM);
    tc2_gemm<false, true, 0><<<gP, 256, SMEM1>>>(
        p_aoh, woh, bo, x, p_h, nullptr, NTOK, DM, DM);

    // 5) LN2 -> fp16
    ln_kernel<<<NTOK, 256>>>(p_h, ln2a, ln2b, p_n2h, p_n2l);

    // 6) FFN up + ReLU -> f1 fp16 (1-term)
    tc2_gemm<true, false, 1><<<dim3(DFF / GBN, NTOK / GBM), 256, SMEM1>>>(
        p_n2h, w1h, b1, nullptr, nullptr, p_f1h, NTOK, DFF, DM);

    // 7) FFN down + residual(h) -> out fp32 (1-term)
    tc2_gemm<false, true, 0><<<dim3(DM / GBN, NTOK / GBM), 256, SMEM1>>>(
        p_f1h, w2h, b2, p_h, out, nullptr, NTOK, DM, DFF);
}

// round 14
// speedup vs baseline: 1.4548x; 1.4548x over previous
#include <cuda_runtime.h>
#include <cuda_fp16.h>
#include <math.h>
#include <cstdint>

#define S_LEN 2048
#define BATCH 2
#define DM    1024
#define NHEAD 16
#define DKH   64
#define DFF   4096
#define NTOK  (BATCH * S_LEN)   // 4096
#define LN_EPS 1e-6f

#define GBM 128
#define GBN 128
#define GBK 64

__device__ __forceinline__ uint32_t smem_u32(const void* p) {
    uint32_t a;
    asm("{ .reg .u64 t; cvta.to.shared.u64 t, %1; cvt.u32.u64 %0, t; }"
        : "=r"(a) : "l"(p));
    return a;
}
__device__ __forceinline__ void ldsm_x4(uint32_t addr, uint32_t& r0, uint32_t& r1,
                                        uint32_t& r2, uint32_t& r3) {
    asm volatile("ldmatrix.sync.aligned.m8n8.x4.shared.b16 {%0,%1,%2,%3}, [%4];"
                 : "=r"(r0), "=r"(r1), "=r"(r2), "=r"(r3) : "r"(addr));
}
__device__ __forceinline__ void ldsm_x4_t(uint32_t addr, uint32_t& r0, uint32_t& r1,
                                          uint32_t& r2, uint32_t& r3) {
    asm volatile("ldmatrix.sync.aligned.m8n8.x4.trans.shared.b16 {%0,%1,%2,%3}, [%4];"
                 : "=r"(r0), "=r"(r1), "=r"(r2), "=r"(r3) : "r"(addr));
}
__device__ __forceinline__ void mma_f16(float* c, uint32_t a0, uint32_t a1,
                                        uint32_t a2, uint32_t a3,
                                        uint32_t b0, uint32_t b1) {
    asm volatile(
        "mma.sync.aligned.m16n8k16.row.col.f32.f16.f16.f32 "
        "{%0,%1,%2,%3}, {%4,%5,%6,%7}, {%8,%9}, {%0,%1,%2,%3};"
        : "+f"(c[0]), "+f"(c[1]), "+f"(c[2]), "+f"(c[3])
        : "r"(a0), "r"(a1), "r"(a2), "r"(a3), "r"(b0), "r"(b1));
}
#define CP_ASYNC16(dst, src) \
    asm volatile("cp.async.cg.shared.global [%0], [%1], 16;" :: "r"(dst), "l"(src))
#define CP_COMMIT() asm volatile("cp.async.commit_group;" ::: "memory")
#define CP_WAIT0()  asm volatile("cp.async.wait_group 0;" ::: "memory")

// ---------------- scratch (device globals; no allocation) ----------------
__device__ __half g_n1h[NTOK * DM];
__device__ __half g_n1l[NTOK * DM];
__device__ __half g_qh[NTOK * DM], g_ql[NTOK * DM];
__device__ __half g_kh[NTOK * DM], g_kl[NTOK * DM];
__device__ __half g_vh[NTOK * DM];
__device__ __half g_aoh[NTOK * DM];
__device__ float  g_h [NTOK * DM];
__device__ __half g_n2h[NTOK * DM];
__device__ __half g_n2l[NTOK * DM];
__device__ __half g_f1h[NTOK * DFF];
__device__ __half g_wqkvh[3 * DM * DM], g_wqkvl[3 * DM * DM];
__device__ __half g_woh[DM * DM];
__device__ __half g_w1h[DM * DFF];
__device__ __half g_w2h[DFF * DM];

// ---------------- weight transpose + fp16 hi/lo split ---------------------
template<bool WANT_LO>
__global__ void __launch_bounds__(256) wsplit_kernel(
    const float* __restrict__ W, __half* __restrict__ Bh, __half* __restrict__ Bl,
    int K, int N)
{
    __shared__ float tile[32][33];
    int n0 = blockIdx.x * 32, k0 = blockIdx.y * 32;
    int tx = threadIdx.x & 31, ty = threadIdx.x >> 5;
#pragma unroll
    for (int i = 0; i < 4; i++)
        tile[ty + 8 * i][tx] = W[(size_t)(k0 + ty + 8 * i) * N + n0 + tx];
    __syncthreads();
#pragma unroll
    for (int i = 0; i < 4; i++) {
        int nl = ty + 8 * i;
        float w = tile[tx][nl];
        __half h = __float2half_rn(w);
        size_t o = (size_t)(n0 + nl) * K + k0 + tx;
        Bh[o] = h;
        if (WANT_LO) {
            __half l = __float2half_rn(w - __half2float(h));
            Bl[o] = l;
        }
    }
}

// 4 square 1024x1024 weights in one launch (lo only for Q/K/V sections)
__global__ void __launch_bounds__(256) wsplit4_kernel(
    const float* __restrict__ Wq, const float* __restrict__ Wk,
    const float* __restrict__ Wv, const float* __restrict__ Wo,
    __half* __restrict__ qkvh, __half* __restrict__ qkvl,
    __half* __restrict__ woh)
{
    __shared__ float tile[32][33];
    int z = blockIdx.z;
    const float* W = (z == 0) ? Wq : (z == 1) ? Wk : (z == 2) ? Wv : Wo;
    __half* Bh = (z < 3) ? (qkvh + (size_t)z * DM * DM) : woh;
    __half* Bl = (z < 3) ? (qkvl + (size_t)z * DM * DM) : nullptr;
    int n0 = blockIdx.x * 32, k0 = blockIdx.y * 32;
    int tx = threadIdx.x & 31, ty = threadIdx.x >> 5;
#pragma unroll
    for (int i = 0; i < 4; i++)
        tile[ty + 8 * i][tx] = W[(size_t)(k0 + ty + 8 * i) * DM + n0 + tx];
    __syncthreads();
#pragma unroll
    for (int i = 0; i < 4; i++) {
        int nl = ty + 8 * i;
        float w = tile[tx][nl];
        __half h = __float2half_rn(w);
        size_t o = (size_t)(n0 + nl) * DM + k0 + tx;
        Bh[o] = h;
        if (z < 3) {
            __half l = __float2half_rn(w - __half2float(h));
            Bl[o] = l;
        }
    }
}

// ---------------- LayerNorm -> fp16 hi/lo ---------------------------------
__global__ void __launch_bounds__(256) ln_kernel(
    const float* __restrict__ x, const float* __restrict__ alpha,
    const float* __restrict__ beta, __half* __restrict__ yh,
    __half* __restrict__ yl)
{
    int row = blockIdx.x;
    int tid = threadIdx.x;
    const float4* x4 = (const float4*)(x + (size_t)row * DM);
    float4 v = x4[tid];
    float s = v.x + v.y + v.z + v.w;
    float q = v.x * v.x + v.y * v.y + v.z * v.z + v.w * v.w;

    __shared__ float rs[8], rq[8];
#pragma unroll
    for (int o = 16; o; o >>= 1) {
        s += __shfl_xor_sync(0xffffffffu, s, o);
        q += __shfl_xor_sync(0xffffffffu, q, o);
    }
    if ((tid & 31) == 0) { rs[tid >> 5] = s; rq[tid >> 5] = q; }
    __syncthreads();
    s = 0.f; q = 0.f;
#pragma unroll
    for (int i = 0; i < 8; i++) { s += rs[i]; q += rq[i]; }

    float mean = s * (1.0f / DM);
    float var  = (q - (float)DM * mean * mean) * (1.0f / (DM - 1));
    float a    = alpha[0];
    float b    = beta[0];
    float inv  = a / (sqrtf(var) + LN_EPS);

    float o0 = (v.x - mean) * inv + b;
    float o1 = (v.y - mean) * inv + b;
    float o2 = (v.z - mean) * inv + b;
    float o3 = (v.w - mean) * inv + b;

    __half2 h0 = __floats2half2_rn(o0, o1);
    __half2 h1 = __floats2half2_rn(o2, o3);
    float2 hf0 = __half22float2(h0), hf1 = __half22float2(h1);
    __half2 l0 = __floats2half2_rn(o0 - hf0.x, o1 - hf0.y);
    __half2 l1 = __floats2half2_rn(o2 - hf1.x, o3 - hf1.y);

    uint2 uh, ul;
    uh.x = *(uint32_t*)&h0; uh.y = *(uint32_t*)&h1;
    ul.x = *(uint32_t*)&l0; ul.y = *(uint32_t*)&l1;
    *(uint2*)(yh + (size_t)row * DM + tid * 4) = uh;
    *(uint2*)(yl + (size_t)row * DM + tid * 4) = ul;
}

// ---------------- 1-term HMMA GEMM (Wo / FFN) -----------------------------
template<bool RELU, bool RES, int OUT>
__global__ void __launch_bounds__(256, 2) tc2_gemm(
    const __half* __restrict__ Ah, const __half* __restrict__ Bh,
    const float* __restrict__ bias, const float* __restrict__ res,
    float* __restrict__ Cf, __half* __restrict__ Ch,
    int M, int N, int K)
{
    extern __shared__ char sm[];
    constexpr uint32_t AH_OFF = 0;
    constexpr uint32_t BH_OFF = 16384u;
    constexpr uint32_t STAGE = 32768u;

    const int tid = threadIdx.x;
    const int wid = tid >> 5;
    const int lid = tid & 31;
    const int nb = blockIdx.x, mb = blockIdx.y;

    const int warp_m = (wid >> 2) * 64;
    const int warp_n = (wid & 3) * 32;

    const uint32_t smb = smem_u32(sm);

    const int a_row = warp_m + (lid & 15);
    const uint32_t a_cb = (uint32_t)((lid >> 4) * 16);
    const int b_row_off = ((lid & 16) >> 1) + (lid & 7);
    const uint32_t b_cb = (lid & 8) ? 16u : 0u;
    const uint32_t xm = (uint32_t)((lid & 7) << 4);

    float acc[4][4][4];
#pragma unroll
    for (int i = 0; i < 4; i++)
#pragma unroll
        for (int j = 0; j < 4; j++)
#pragma unroll
            for (int r = 0; r < 4; r++) acc[i][j][r] = 0.f;

    const int sj = tid & 7;
    const int sr0 = tid >> 3;
    const int niter = K / GBK;

    auto stage = [&](int kt, int buf) {
        uint32_t base = smb + (uint32_t)buf * STAGE;
#pragma unroll
        for (int i = 0; i < 4; i++) {
            int r = i * 32 + sr0;
            uint32_t sw = (uint32_t)(r * 128 + ((sj * 16) ^ ((r & 7) << 4)));
            CP_ASYNC16(base + AH_OFF + sw, Ah + (size_t)(mb * GBM + r) * K + kt * GBK + sj * 8);
            CP_ASYNC16(base + BH_OFF + sw, Bh + (size_t)(nb * GBN + r) * K + kt * GBK + sj * 8);
        }
    };

    stage(0, 0);
    CP_COMMIT();

    for (int kt = 0; kt < niter; kt++) {
        int buf = kt & 1;
        CP_WAIT0();
        __syncthreads();
        if (kt + 1 < niter) {
            stage(kt + 1, buf ^ 1);
            CP_COMMIT();
        }

        uint32_t ah_u = smb + (uint32_t)buf * STAGE + AH_OFF;
        uint32_t bh_u = smb + (uint32_t)buf * STAGE + BH_OFF;

#pragma unroll
        for (int s = 0; s < 4; s++) {
            uint32_t bhf[8];
#pragma unroll
            for (int pr = 0; pr < 2; pr++) {
                uint32_t roff = (uint32_t)(warp_n + pr * 16 + b_row_off) * 128;
                uint32_t coff = (uint32_t)(s * 32 + b_cb) ^ xm;
                ldsm_x4(bh_u + roff + coff, bhf[pr*4+0], bhf[pr*4+1], bhf[pr*4+2], bhf[pr*4+3]);
            }
#pragma unroll
            for (int mt = 0; mt < 4; mt++) {
                uint32_t roff = (uint32_t)(a_row + mt * 16) * 128;
                uint32_t coff = (uint32_t)(s * 32 + a_cb) ^ xm;
                uint32_t a0, a1, a2, a3;
                ldsm_x4(ah_u + roff + coff, a0, a1, a2, a3);
#pragma unroll
                for (int nt = 0; nt < 4; nt++) {
                    uint32_t hb0 = bhf[(nt >> 1) * 4 + (nt & 1) * 2];
                    uint32_t hb1 = bhf[(nt >> 1) * 4 + (nt & 1) * 2 + 1];
                    mma_f16(acc[mt][nt], a0, a1, a2, a3, hb0, hb1);
                }
            }
        }
        __syncthreads();
    }

    {
        int g = lid >> 2, tig = lid & 3;
        int base_row = mb * GBM + warp_m + g;
        int base_col = nb * GBN + warp_n + tig * 2;
#pragma unroll
        for (int mt = 0; mt < 4; mt++) {
#pragma unroll
            for (int nt = 0; nt < 4; nt++) {
                int col = base_col + nt * 8;
                float2 bb = *(const float2*)(bias + col);
#pragma unroll
                for (int hrow = 0; hrow < 2; hrow++) {
                    int row = base_row + mt * 16 + hrow * 8;
                    float2 o;
                    o.x = acc[mt][nt][hrow * 2 + 0] + bb.x;
                    o.y = acc[mt][nt][hrow * 2 + 1] + bb.y;
                    if (RES) {
                        float2 r2 = *(const float2*)(res + (size_t)row * N + col);
                        o.x += r2.x; o.y += r2.y;
                    }
                    if (RELU) {
                        o.x = fmaxf(o.x, 0.f);
                        o.y = fmaxf(o.y, 0.f);
                    }
                    if (OUT == 0) {
                        *(float2*)(Cf + (size_t)row * N + col) = o;
                    } else {
                        __half2 hv = __floats2half2_rn(o.x, o.y);
                        *(__half2*)(Ch + (size_t)row * N + col) = hv;
                    }
                }
            }
        }
    }
}

// ---------------- fused QKV GEMM (M64, double-buffered) --------------------
// Q/K sections: 3-term + hi/lo output. V: 2-term, fp16 output.
__global__ void __launch_bounds__(256, 2) tc_qkv_gemm(
    const __half* __restrict__ Ah, const __half* __restrict__ Al,
    const __half* __restrict__ Bh, const __half* __restrict__ Bl,
    const float* __restrict__ bq, const float* __restrict__ bk,
    const float* __restrict__ bv,
    __half* __restrict__ Qh, __half* __restrict__ Ql,
    __half* __restrict__ Kh, __half* __restrict__ Kl,
    __half* __restrict__ Vh)
{
    extern __shared__ char sm[];
    constexpr uint32_t AH_OFF = 0;
    constexpr uint32_t AL_OFF = 8192u;
    constexpr uint32_t BH_OFF = 16384u;
    constexpr uint32_t BL_OFF = 32768u;
    const uint32_t STAGE = 49152u;
    const int K = DM;

    const int tid = threadIdx.x;
    const int wid = tid >> 5;
    const int lid = tid & 31;
    const int nb = blockIdx.x, mb = blockIdx.y;
    const int sect = nb >> 3;
    const bool three_term = (sect < 2);

    const int warp_m = (wid >> 2) * 32;
    const int warp_n = (wid & 3) * 32;

    const uint32_t smb = smem_u32(sm);

    const int a_row = warp_m + (lid & 15);
    const uint32_t a_cb = (uint32_t)((lid >> 4) * 16);
    const int b_row_off = ((lid & 16) >> 1) + (lid & 7);
    const uint32_t b_cb = (lid & 8) ? 16u : 0u;
    const uint32_t xm = (uint32_t)((lid & 7) << 4);

    float acc[2][4][4];
#pragma unroll
    for (int i = 0; i < 2; i++)
#pragma unroll
        for (int j = 0; j < 4; j++)
#pragma unroll
            for (int r = 0; r < 4; r++) acc[i][j][r] = 0.f;

    const int sj = tid & 7;
    const int sr0 = tid >> 3;
    const int niter = K / GBK;

    auto stage = [&](int kt, int buf) {
        uint32_t base = smb + (uint32_t)buf * STAGE;
#pragma unroll
        for (int i = 0; i < 2; i++) {
            int r = i * 32 + sr0;
            uint32_t sw = (uint32_t)(r * 128 + ((sj * 16) ^ ((r & 7) << 4)));
            CP_ASYNC16(base + AH_OFF + sw, Ah + (size_t)(mb * 64 + r) * K + kt * GBK + sj * 8);
            if (three_term)
                CP_ASYNC16(base + AL_OFF + sw, Al + (size_t)(mb * 64 + r) * K + kt * GBK + sj * 8);
        }
#pragma unroll
        for (int i = 0; i < 4; i++) {
            int r = i * 32 + sr0;
            uint32_t sw = (uint32_t)(r * 128 + ((sj * 16) ^ ((r & 7) << 4)));
            CP_ASYNC16(base + BH_OFF + sw, Bh + (size_t)(nb * GBN + r) * K + kt * GBK + sj * 8);
            CP_ASYNC16(base + BL_OFF + sw, Bl + (size_t)(nb * GBN + r) * K + kt * GBK + sj * 8);
        }
    };

    stage(0, 0);
    CP_COMMIT();

    for (int kt = 0; kt < niter; kt++) {
        int buf = kt & 1;
        CP_WAIT0();
        __syncthreads();
        if (kt + 1 < niter) {
            stage(kt + 1, buf ^ 1);
            CP_COMMIT();
        }

        uint32_t ah_u = smb + (uint32_t)buf * STAGE + AH_OFF;
        uint32_t al_u = smb + (uint32_t)buf * STAGE + AL_OFF;
        uint32_t bh_u = smb + (uint32_t)buf * STAGE + BH_OFF;
        uint32_t bl_u = smb + (uint32_t)buf * STAGE + BL_OFF;

#pragma unroll
        for (int s = 0; s < 4; s++) {
            uint32_t bhf[8], blf[8];
#pragma unroll
            for (int pr = 0; pr < 2; pr++) {
                uint32_t roff = (uint32_t)(warp_n + pr * 16 + b_row_off) * 128;
                uint32_t coff = (uint32_t)(s * 32 + b_cb) ^ xm;
                ldsm_x4(bh_u + roff + coff, bhf[pr*4+0], bhf[pr*4+1], bhf[pr*4+2], bhf[pr*4+3]);
                ldsm_x4(bl_u + roff + coff, blf[pr*4+0], blf[pr*4+1], blf[pr*4+2], blf[pr*4+3]);
            }
#pragma unroll
            for (int mt = 0; mt < 2; mt++) {
                uint32_t roff = (uint32_t)(a_row + mt * 16) * 128;
                uint32_t coff = (uint32_t)(s * 32 + a_cb) ^ xm;
                uint32_t a0, a1, a2, a3, l0, l1, l2, l3;
                ldsm_x4(ah_u + roff + coff, a0, a1, a2, a3);
                if (three_term)
                    ldsm_x4(al_u + roff + coff, l0, l1, l2, l3);
#pragma unroll
                for (int nt = 0; nt < 4; nt++) {
                    uint32_t hb0 = bhf[(nt >> 1) * 4 + (nt & 1) * 2];
                    uint32_t hb1 = bhf[(nt >> 1) * 4 + (nt & 1) * 2 + 1];
                    uint32_t lb0 = blf[(nt >> 1) * 4 + (nt & 1) * 2];
                    uint32_t lb1 = blf[(nt >> 1) * 4 + (nt & 1) * 2 + 1];
                    mma_f16(acc[mt][nt], a0, a1, a2, a3, hb0, hb1);
                    mma_f16(acc[mt][nt], a0, a1, a2, a3, lb0, lb1);
                    if (three_term)
                        mma_f16(acc[mt][nt], l0, l1, l2, l3, hb0, hb1);
                }
            }
        }
        __syncthreads();
    }

    {
        int nb_l = nb & 7;
        const float* bp = (sect == 0) ? bq : ((sect == 1) ? bk : bv);
        __half* Dh = (sect == 0) ? Qh : ((sect == 1) ? Kh : Vh);
        __half* Dl = (sect == 0) ? Ql : Kl;

        int g = lid >> 2, tig = lid & 3;
        int base_row = mb * 64 + warp_m + g;
        int base_col = nb_l * GBN + warp_n + tig * 2;
#pragma unroll
        for (int mt = 0; mt < 2; mt++) {
#pragma unroll
            for (int nt = 0; nt < 4; nt++) {
                int col = base_col + nt * 8;
                float2 bb = *(const float2*)(bp + col);
#pragma unroll
                for (int hrow = 0; hrow < 2; hrow++) {
                    int row = base_row + mt * 16 + hrow * 8;
                    float ox = acc[mt][nt][hrow * 2 + 0] + bb.x;
                    float oy = acc[mt][nt][hrow * 2 + 1] + bb.y;
                    __half2 hv = __floats2half2_rn(ox, oy);
                    *(__half2*)(Dh + (size_t)row * DM + col) = hv;
                    if (sect < 2) {
                        float2 hf = __half22float2(hv);
                        __half2 lv = __floats2half2_rn(ox - hf.x, oy - hf.y);
                        *(__half2*)(Dl + (size_t)row * DM + col) = lv;
                    }
                }
            }
        }
    }
}

// ---------------- HMMA flash attention (double-buffered K/V) --------------
#define AQH 0u
#define AQL 16384u
#define ABUF0 32768u
#define ABUFSZ 24576u
#define APB 81920u
#define ATTN_SMEM 98304

__global__ void __launch_bounds__(256, 2) fattn_mma(
    const __half* __restrict__ Qh, const __half* __restrict__ Ql,
    const __half* __restrict__ Kh, const __half* __restrict__ Kl,
    const __half* __restrict__ Vh, __half* __restrict__ Oh)
{
    extern __shared__ char sm[];
    const uint32_t smb = smem_u32(sm);

    const int tid = threadIdx.x;
    const int wid = tid >> 5;
    const int lid = tid & 31;
    const int h = blockIdx.y, b = blockIdx.z;
    const int q0 = blockIdx.x * 128;

    const int warp_m = wid * 16;

    const int a_row = warp_m + (lid & 15);
    const uint32_t a_cb = (uint32_t)((lid >> 4) * 16);
    const int b_row_off = ((lid & 16) >> 1) + (lid & 7);
    const uint32_t b_cb = (lid & 8) ? 16u : 0u;
    const uint32_t xm = (uint32_t)((lid & 7) << 4);

    const int v_krow = lid & 15;
    const uint32_t v_db = (uint32_t)((lid >> 4) << 4);

    const size_t bh_off = ((size_t)b * S_LEN) * DM + h * DKH;

    const int sj = tid & 7;
    const int sr0 = tid >> 3;

    {
#pragma unroll
        for (int i = 0; i < 4; i++) {
            int r = sr0 + i * 32;
            uint32_t sw = (uint32_t)(r * 128 + ((sj * 16) ^ ((r & 7) << 4)));
            CP_ASYNC16(smb + AQH + sw, Qh + bh_off + (size_t)(q0 + r) * DM + sj * 8);
            CP_ASYNC16(smb + AQL + sw, Ql + bh_off + (size_t)(q0 + r) * DM + sj * 8);
        }
        CP_COMMIT();
    }

    auto stage_kv = [&](int k0, int buf) {
        uint32_t base = smb + ABUF0 + (uint32_t)buf * ABUFSZ;
#pragma unroll
        for (int i = 0; i < 2; i++) {
            int r = sr0 + i * 32;
            uint32_t sw = (uint32_t)(r * 128 + ((sj * 16) ^ ((r & 7) << 4)));
            CP_ASYNC16(base + sw,          Kh + bh_off + (size_t)(k0 + r) * DM + sj * 8);
            CP_ASYNC16(base + 8192u + sw,  Kl + bh_off + (size_t)(k0 + r) * DM + sj * 8);
            CP_ASYNC16(base + 16384u + sw, Vh + bh_off + (size_t)(k0 + r) * DM + sj * 8);
        }
    };

    stage_kv(0, 0);
    CP_COMMIT();

    float Oa[8][4];
    float mrow[2], lrow[2];
#pragma unroll
    for (int nt = 0; nt < 8; nt++)
#pragma unroll
        for (int r = 0; r < 4; r++) Oa[nt][r] = 0.f;
    mrow[0] = mrow[1] = -INFINITY;
    lrow[0] = lrow[1] = 0.f;

    CP_WAIT0();
    __syncthreads();

    const int NT = S_LEN / 64;
    for (int t = 0; t < NT; t++) {
        int buf = t & 1;
        uint32_t kh_u = smb + ABUF0 + (uint32_t)buf * ABUFSZ;
        uint32_t kl_u = kh_u + 8192u;
        uint32_t vs_u = kh_u + 16384u;

        if (t + 1 < NT) {
            stage_kv((t + 1) * 64, buf ^ 1);
            CP_COMMIT();
        }

        float sacc[8][4];
#pragma unroll
        for (int nt = 0; nt < 8; nt++)
#pragma unroll
            for (int r = 0; r < 4; r++) sacc[nt][r] = 0.f;

#pragma unroll
        for (int s = 0; s < 4; s++) {
            uint32_t acoff = (uint32_t)(s * 32 + a_cb) ^ xm;
            uint32_t qa0, qa1, qa2, qa3, la0, la1, la2, la3;
            ldsm_x4(smb + AQH + (uint32_t)a_row * 128 + acoff, qa0, qa1, qa2, qa3);
            ldsm_x4(smb + AQL + (uint32_t)a_row * 128 + acoff, la0, la1, la2, la3);
            uint32_t bcoff = (uint32_t)(s * 32 + b_cb) ^ xm;
#pragma unroll
            for (int pr = 0; pr < 4; pr++) {
                uint32_t roff = (uint32_t)(pr * 16 + b_row_off) * 128;
                uint32_t h0, h1, h2, h3, l0, l1, l2, l3;
                ldsm_x4(kh_u + roff + bcoff, h0, h1, h2, h3);
                ldsm_x4(kl_u + roff + bcoff, l0, l1, l2, l3);
                mma_f16(sacc[pr*2+0], qa0, qa1, qa2, qa3, h0, h1);
                mma_f16(sacc[pr*2+0], qa0, qa1, qa2, qa3, l0, l1);
                mma_f16(sacc[pr*2+0], la0, la1, la2, la3, h0, h1);
                mma_f16(sacc[pr*2+1], qa0, qa1, qa2, qa3, h2, h3);
                mma_f16(sacc[pr*2+1], qa0, qa1, qa2, qa3, l2, l3);
                mma_f16(sacc[pr*2+1], la0, la1, la2, la3, h2, h3);
            }
        }

        float corr0, corr1;
#pragma unroll
        for (int r = 0; r < 2; r++) {
            float mx = -INFINITY;
#pragma unroll
            for (int nt = 0; nt < 8; nt++) {
                mx = fmaxf(mx, sacc[nt][r*2+0]);
                mx = fmaxf(mx, sacc[nt][r*2+1]);
            }
            mx = fmaxf(mx, __shfl_xor_sync(0xffffffffu, mx, 1));
            mx = fmaxf(mx, __shfl_xor_sync(0xffffffffu, mx, 2));
            float mn = fmaxf(mrow[r], mx);
            float c = __expf(mrow[r] - mn);
            mrow[r] = mn;
            float sum = 0.f;
#pragma unroll
            for (int nt = 0; nt < 8; nt++) {
                float e0 = __expf(sacc[nt][r*2+0] - mn);
                float e1 = __expf(sacc[nt][r*2+1] - mn);
                sacc[nt][r*2+0] = e0;
                sacc[nt][r*2+1] = e1;
                sum += e0 + e1;
            }
            sum += __shfl_xor_sync(0xffffffffu, sum, 1);
            sum += __shfl_xor_sync(0xffffffffu, sum, 2);
            lrow[r] = lrow[r] * c + sum;
            if (r == 0) corr0 = c; else corr1 = c;
        }
#pragma unroll
        for (int nt = 0; nt < 8; nt++) {
            Oa[nt][0] *= corr0; Oa[nt][1] *= corr0;
            Oa[nt][2] *= corr1; Oa[nt][3] *= corr1;
        }

        __syncwarp();
        {
            int g = lid >> 2, tig = lid & 3;
            int row0 = warp_m + g;
            int row1 = row0 + 8;
            uint32_t x0 = (uint32_t)((row0 & 7) << 4);
            uint32_t x1 = (uint32_t)((row1 & 7) << 4);
#pragma unroll
            for (int nt = 0; nt < 8; nt++) {
                int col = tig * 2 + nt * 8;
                __half2 p0 = __floats2half2_rn(sacc[nt][0], sacc[nt][1]);
                __half2 p1 = __floats2half2_rn(sacc[nt][2], sacc[nt][3]);
                *(__half2*)(sm + APB + (uint32_t)(row0 * 128 + ((col * 2) ^ x0))) = p0;
                *(__half2*)(sm + APB + (uint32_t)(row1 * 128 + ((col * 2) ^ x1))) = p1;
            }
        }
        __syncwarp();

#pragma unroll
        for (int s = 0; s < 4; s++) {
            uint32_t acoff = (uint32_t)(s * 32 + a_cb) ^ xm;
            uint32_t pa0, pa1, pa2, pa3;
            ldsm_x4(smb + APB + (uint32_t)a_row * 128 + acoff, pa0, pa1, pa2, pa3);
            int krow = s * 16 + v_krow;
#pragma unroll
            for (int pr = 0; pr < 4; pr++) {
                uint32_t vaddr = vs_u + (uint32_t)krow * 128 +
                                 (((uint32_t)(pr * 32) + v_db) ^ ((uint32_t)(krow & 7) << 4));
                uint32_t v0, v1, v2, v3;
                ldsm_x4_t(vaddr, v0, v1, v2, v3);
                mma_f16(Oa[pr*2+0], pa0, pa1, pa2, pa3, v0, v1);
                mma_f16(Oa[pr*2+1], pa0, pa1, pa2, pa3, v2, v3);
            }
        }

        if (t + 1 < NT) CP_WAIT0();
        __syncthreads();
    }

    {
        int g = lid >> 2, tig = lid & 3;
        float inv0 = 1.0f / lrow[0];
        float inv1 = 1.0f / lrow[1];
        int row0 = q0 + warp_m + g;
        int row1 = row0 + 8;
#pragma unroll
        for (int nt = 0; nt < 8; nt++) {
            int col = tig * 2 + nt * 8;
            __half2 o0 = __floats2half2_rn(Oa[nt][0] * inv0, Oa[nt][1] * inv0);
            __half2 o1 = __floats2half2_rn(Oa[nt][2] * inv1, Oa[nt][3] * inv1);
            *(__half2*)(Oh + bh_off + (size_t)row0 * DM + col) = o0;
            *(__half2*)(Oh + bh_off + (size_t)row1 * DM + col) = o1;
        }
    }
}

// ---------------- launch ----------------
extern "C" void kernel_launch(void* const* d_in, const int* in_sizes, int n_in,
                              void* d_out, int out_size)
{
    const float* x    = (const float*)d_in[0];
    const float* Wq   = (const float*)d_in[1];
    const float* bq   = (const float*)d_in[2];
    const float* Wk   = (const float*)d_in[3];
    const float* bk   = (const float*)d_in[4];
    const float* Wv   = (const float*)d_in[5];
    const float* bv   = (const float*)d_in[6];
    const float* Wo   = (const float*)d_in[7];
    const float* bo   = (const float*)d_in[8];
    const float* W1   = (const float*)d_in[9];
    const float* b1   = (const float*)d_in[10];
    const float* W2   = (const float*)d_in[11];
    const float* b2   = (const float*)d_in[12];
    const float* ln1a = (const float*)d_in[13];
    const float* ln1b = (const float*)d_in[14];
    const float* ln2a = (const float*)d_in[15];
    const float* ln2b = (const float*)d_in[16];
    float* out = (float*)d_out;

    __half *p_n1h, *p_n1l, *p_qh, *p_ql, *p_kh, *p_kl, *p_vh;
    __half *p_aoh, *p_n2h, *p_n2l, *p_f1h;
    float *p_h;
    __half *wqkvh, *wqkvl, *woh, *w1h, *w2h;
    cudaGetSymbolAddress((void**)&p_n1h, g_n1h);
    cudaGetSymbolAddress((void**)&p_n1l, g_n1l);
    cudaGetSymbolAddress((void**)&p_qh, g_qh);
    cudaGetSymbolAddress((void**)&p_ql, g_ql);
    cudaGetSymbolAddress((void**)&p_kh, g_kh);
    cudaGetSymbolAddress((void**)&p_kl, g_kl);
    cudaGetSymbolAddress((void**)&p_vh, g_vh);
    cudaGetSymbolAddress((void**)&p_aoh, g_aoh);
    cudaGetSymbolAddress((void**)&p_h,  g_h);
    cudaGetSymbolAddress((void**)&p_n2h, g_n2h);
    cudaGetSymbolAddress((void**)&p_n2l, g_n2l);
    cudaGetSymbolAddress((void**)&p_f1h, g_f1h);
    cudaGetSymbolAddress((void**)&wqkvh, g_wqkvh);
    cudaGetSymbolAddress((void**)&wqkvl, g_wqkvl);
    cudaGetSymbolAddress((void**)&woh, g_woh);
    cudaGetSymbolAddress((void**)&w1h, g_w1h);
    cudaGetSymbolAddress((void**)&w2h, g_w2h);

    const int SMEM1 = 2 * 2 * 16384;   // 64KB (1-term, 2 stages)
    const int SMEMQ = 2 * 49152;       // 96KB (QKV)

    cudaFuncSetAttribute(fattn_mma,
                         cudaFuncAttributeMaxDynamicSharedMemorySize, ATTN_SMEM);
    cudaFuncSetAttribute(tc_qkv_gemm,
                         cudaFuncAttributeMaxDynamicSharedMemorySize, SMEMQ);
    cudaFuncSetAttribute(tc2_gemm<false, true, 0>,
                         cudaFuncAttributeMaxDynamicSharedMemorySize, SMEM1);
    cudaFuncSetAttribute(tc2_gemm<true, false, 1>,
                         cudaFuncAttributeMaxDynamicSharedMemorySize, SMEM1);

    // 0) weight transpose + split (lo only where needed: Q/K/V)
    wsplit4_kernel<<<dim3(DM / 32, DM / 32, 4), 256>>>(
        Wq, Wk, Wv, Wo, wqkvh, wqkvl, woh);
    wsplit_kernel<false><<<dim3(DFF / 32, DM / 32), 256>>>(W1, w1h, nullptr, DM, DFF);
    wsplit_kernel<false><<<dim3(DM / 32, DFF / 32), 256>>>(W2, w2h, nullptr, DFF, DM);

    // 1) LN1 -> fp16 hi/lo
    ln_kernel<<<NTOK, 256>>>(x, ln1a, ln1b, p_n1h, p_n1l);

    // 2) fused QKV projection (3-term for Q/K, 2-term for V)
    tc_qkv_gemm<<<dim3(3 * DM / GBN, NTOK / 64), 256, SMEMQ>>>(
        p_n1h, p_n1l, wqkvh, wqkvl, bq, bk, bv,
        p_qh, p_ql, p_kh, p_kl, p_vh);

    // 3) HMMA flash attention (3-term QK; no 1/sqrt(dk) scaling)
    fattn_mma<<<dim3(S_LEN / 128, NHEAD, BATCH), 256, ATTN_SMEM>>>(
        p_qh, p_ql, p_kh, p_kl, p_vh, p_aoh);

    // 4) output projection + residual(x) -> h fp32 (1-term fp16)
    dim3 gP(DM / GBN, NTOK / GBM);
    tc2_gemm<false, true, 0><<<gP, 256, SMEM1>>>(
        p_aoh, woh, bo, x, p_h, nullptr, NTOK, DM, DM);

    // 5) LN2 -> fp16
    ln_kernel<<<NTOK, 256>>>(p_h, ln2a, ln2b, p_n2h, p_n2l);

    // 6) FFN up + ReLU -> f1 fp16 (1-term fp16)
    tc2_gemm<true, false, 1><<<dim3(DFF / GBN, NTOK / GBM), 256, SMEM1>>>(
        p_n2h, w1h, b1, nullptr, nullptr, p_f1h, NTOK, DFF, DM);

    // 7) FFN down + residual(h) -> out fp32 (1-term fp16)
    tc2_gemm<false, true, 0><<<dim3(DM / GBN, NTOK / GBM), 256, SMEM1>>>(
        p_f1h, w2h, b2, p_h, out, nullptr, NTOK, DM, DFF);
}

// round 15
// speedup vs baseline: 1.5428x; 1.0605x over previous
#include <cuda_runtime.h>
#include <cuda_fp16.h>
#include <math.h>
#include <cstdint>

#define S_LEN 2048
#define BATCH 2
#define DM    1024
#define NHEAD 16
#define DKH   64
#define DFF   4096
#define NTOK  (BATCH * S_LEN)   // 4096
#define LN_EPS 1e-6f

#define GBM 128
#define GBN 128
#define GBK 64

__device__ __forceinline__ uint32_t smem_u32(const void* p) {
    uint32_t a;
    asm("{ .reg .u64 t; cvta.to.shared.u64 t, %1; cvt.u32.u64 %0, t; }"
        : "=r"(a) : "l"(p));
    return a;
}
__device__ __forceinline__ void ldsm_x4(uint32_t addr, uint32_t& r0, uint32_t& r1,
                                        uint32_t& r2, uint32_t& r3) {
    asm volatile("ldmatrix.sync.aligned.m8n8.x4.shared.b16 {%0,%1,%2,%3}, [%4];"
                 : "=r"(r0), "=r"(r1), "=r"(r2), "=r"(r3) : "r"(addr));
}
__device__ __forceinline__ void ldsm_x4_t(uint32_t addr, uint32_t& r0, uint32_t& r1,
                                          uint32_t& r2, uint32_t& r3) {
    asm volatile("ldmatrix.sync.aligned.m8n8.x4.trans.shared.b16 {%0,%1,%2,%3}, [%4];"
                 : "=r"(r0), "=r"(r1), "=r"(r2), "=r"(r3) : "r"(addr));
}
__device__ __forceinline__ void mma_f16(float* c, uint32_t a0, uint32_t a1,
                                        uint32_t a2, uint32_t a3,
                                        uint32_t b0, uint32_t b1) {
    asm volatile(
        "mma.sync.aligned.m16n8k16.row.col.f32.f16.f16.f32 "
        "{%0,%1,%2,%3}, {%4,%5,%6,%7}, {%8,%9}, {%0,%1,%2,%3};"
        : "+f"(c[0]), "+f"(c[1]), "+f"(c[2]), "+f"(c[3])
        : "r"(a0), "r"(a1), "r"(a2), "r"(a3), "r"(b0), "r"(b1));
}
#define CP_ASYNC16(dst, src) \
    asm volatile("cp.async.cg.shared.global [%0], [%1], 16;" :: "r"(dst), "l"(src))
#define CP_COMMIT() asm volatile("cp.async.commit_group;" ::: "memory")
#define CP_WAIT0()  asm volatile("cp.async.wait_group 0;" ::: "memory")

// ---------------- scratch (device globals; no allocation) ----------------
__device__ __half g_n1h[NTOK * DM];
__device__ __half g_n1l[NTOK * DM];
__device__ __half g_qh[NTOK * DM];
__device__ __half g_kh[NTOK * DM], g_kl[NTOK * DM];
__device__ __half g_vh[NTOK * DM];
__device__ __half g_aoh[NTOK * DM];
__device__ float  g_h [NTOK * DM];
__device__ __half g_n2h[NTOK * DM];
__device__ __half g_n2l[NTOK * DM];
__device__ __half g_f1h[NTOK * DFF];
__device__ __half g_wqkvh[3 * DM * DM], g_wqkvl[3 * DM * DM];
__device__ __half g_woh[DM * DM];
__device__ __half g_w1h[DM * DFF];
__device__ __half g_w2h[DFF * DM];

// ---------------- weight transpose + fp16 (hi only) -----------------------
__global__ void __launch_bounds__(256) wsplit_kernel(
    const float* __restrict__ W, __half* __restrict__ Bh, int K, int N)
{
    __shared__ float tile[32][33];
    int n0 = blockIdx.x * 32, k0 = blockIdx.y * 32;
    int tx = threadIdx.x & 31, ty = threadIdx.x >> 5;
#pragma unroll
    for (int i = 0; i < 4; i++)
        tile[ty + 8 * i][tx] = W[(size_t)(k0 + ty + 8 * i) * N + n0 + tx];
    __syncthreads();
#pragma unroll
    for (int i = 0; i < 4; i++) {
        int nl = ty + 8 * i;
        Bh[(size_t)(n0 + nl) * K + k0 + tx] = __float2half_rn(tile[tx][nl]);
    }
}

// 4 square 1024x1024 weights (lo for the Q/K/V sections; epilogue only uses K's)
__global__ void __launch_bounds__(256) wsplit4_kernel(
    const float* __restrict__ Wq, const float* __restrict__ Wk,
    const float* __restrict__ Wv, const float* __restrict__ Wo,
    __half* __restrict__ qkvh, __half* __restrict__ qkvl,
    __half* __restrict__ woh)
{
    __shared__ float tile[32][33];
    int z = blockIdx.z;
    const float* W = (z == 0) ? Wq : (z == 1) ? Wk : (z == 2) ? Wv : Wo;
    __half* Bh = (z < 3) ? (qkvh + (size_t)z * DM * DM) : woh;
    __half* Bl = (z < 3) ? (qkvl + (size_t)z * DM * DM) : nullptr;
    int n0 = blockIdx.x * 32, k0 = blockIdx.y * 32;
    int tx = threadIdx.x & 31, ty = threadIdx.x >> 5;
#pragma unroll
    for (int i = 0; i < 4; i++)
        tile[ty + 8 * i][tx] = W[(size_t)(k0 + ty + 8 * i) * DM + n0 + tx];
    __syncthreads();
#pragma unroll
    for (int i = 0; i < 4; i++) {
        int nl = ty + 8 * i;
        float w = tile[tx][nl];
        __half h = __float2half_rn(w);
        size_t o = (size_t)(n0 + nl) * DM + k0 + tx;
        Bh[o] = h;
        if (z < 3) {
            __half l = __float2half_rn(w - __half2float(h));
            Bl[o] = l;
        }
    }
}

// ---------------- LayerNorm -> fp16 hi/lo ---------------------------------
__global__ void __launch_bounds__(256) ln_kernel(
    const float* __restrict__ x, const float* __restrict__ alpha,
    const float* __restrict__ beta, __half* __restrict__ yh,
    __half* __restrict__ yl)
{
    int row = blockIdx.x;
    int tid = threadIdx.x;
    const float4* x4 = (const float4*)(x + (size_t)row * DM);
    float4 v = x4[tid];
    float s = v.x + v.y + v.z + v.w;
    float q = v.x * v.x + v.y * v.y + v.z * v.z + v.w * v.w;

    __shared__ float rs[8], rq[8];
#pragma unroll
    for (int o = 16; o; o >>= 1) {
        s += __shfl_xor_sync(0xffffffffu, s, o);
        q += __shfl_xor_sync(0xffffffffu, q, o);
    }
    if ((tid & 31) == 0) { rs[tid >> 5] = s; rq[tid >> 5] = q; }
    __syncthreads();
    s = 0.f; q = 0.f;
#pragma unroll
    for (int i = 0; i < 8; i++) { s += rs[i]; q += rq[i]; }

    float mean = s * (1.0f / DM);
    float var  = (q - (float)DM * mean * mean) * (1.0f / (DM - 1));
    float a    = alpha[0];
    float b    = beta[0];
    float inv  = a / (sqrtf(var) + LN_EPS);

    float o0 = (v.x - mean) * inv + b;
    float o1 = (v.y - mean) * inv + b;
    float o2 = (v.z - mean) * inv + b;
    float o3 = (v.w - mean) * inv + b;

    __half2 h0 = __floats2half2_rn(o0, o1);
    __half2 h1 = __floats2half2_rn(o2, o3);
    float2 hf0 = __half22float2(h0), hf1 = __half22float2(h1);
    __half2 l0 = __floats2half2_rn(o0 - hf0.x, o1 - hf0.y);
    __half2 l1 = __floats2half2_rn(o2 - hf1.x, o3 - hf1.y);

    uint2 uh, ul;
    uh.x = *(uint32_t*)&h0; uh.y = *(uint32_t*)&h1;
    ul.x = *(uint32_t*)&l0; ul.y = *(uint32_t*)&l1;
    *(uint2*)(yh + (size_t)row * DM + tid * 4) = uh;
    *(uint2*)(yl + (size_t)row * DM + tid * 4) = ul;
}

// ---------------- 1-term HMMA GEMM (Wo / FFN) -----------------------------
template<bool RELU, bool RES, int OUT>
__global__ void __launch_bounds__(256, 2) tc2_gemm(
    const __half* __restrict__ Ah, const __half* __restrict__ Bh,
    const float* __restrict__ bias, const float* __restrict__ res,
    float* __restrict__ Cf, __half* __restrict__ Ch,
    int M, int N, int K)
{
    extern __shared__ char sm[];
    constexpr uint32_t AH_OFF = 0;
    constexpr uint32_t BH_OFF = 16384u;
    constexpr uint32_t STAGE = 32768u;

    const int tid = threadIdx.x;
    const int wid = tid >> 5;
    const int lid = tid & 31;
    const int nb = blockIdx.x, mb = blockIdx.y;

    const int warp_m = (wid >> 2) * 64;
    const int warp_n = (wid & 3) * 32;

    const uint32_t smb = smem_u32(sm);

    const int a_row = warp_m + (lid & 15);
    const uint32_t a_cb = (uint32_t)((lid >> 4) * 16);
    const int b_row_off = ((lid & 16) >> 1) + (lid & 7);
    const uint32_t b_cb = (lid & 8) ? 16u : 0u;
    const uint32_t xm = (uint32_t)((lid & 7) << 4);

    float acc[4][4][4];
#pragma unroll
    for (int i = 0; i < 4; i++)
#pragma unroll
        for (int j = 0; j < 4; j++)
#pragma unroll
            for (int r = 0; r < 4; r++) acc[i][j][r] = 0.f;

    const int sj = tid & 7;
    const int sr0 = tid >> 3;
    const int niter = K / GBK;

    auto stage = [&](int kt, int buf) {
        uint32_t base = smb + (uint32_t)buf * STAGE;
#pragma unroll
        for (int i = 0; i < 4; i++) {
            int r = i * 32 + sr0;
            uint32_t sw = (uint32_t)(r * 128 + ((sj * 16) ^ ((r & 7) << 4)));
            CP_ASYNC16(base + AH_OFF + sw, Ah + (size_t)(mb * GBM + r) * K + kt * GBK + sj * 8);
            CP_ASYNC16(base + BH_OFF + sw, Bh + (size_t)(nb * GBN + r) * K + kt * GBK + sj * 8);
        }
    };

    stage(0, 0);
    CP_COMMIT();

    for (int kt = 0; kt < niter; kt++) {
        int buf = kt & 1;
        CP_WAIT0();
        __syncthreads();
        if (kt + 1 < niter) {
            stage(kt + 1, buf ^ 1);
            CP_COMMIT();
        }

        uint32_t ah_u = smb + (uint32_t)buf * STAGE + AH_OFF;
        uint32_t bh_u = smb + (uint32_t)buf * STAGE + BH_OFF;

#pragma unroll
        for (int s = 0; s < 4; s++) {
            uint32_t bhf[8];
#pragma unroll
            for (int pr = 0; pr < 2; pr++) {
                uint32_t roff = (uint32_t)(warp_n + pr * 16 + b_row_off) * 128;
                uint32_t coff = (uint32_t)(s * 32 + b_cb) ^ xm;
                ldsm_x4(bh_u + roff + coff, bhf[pr*4+0], bhf[pr*4+1], bhf[pr*4+2], bhf[pr*4+3]);
            }
#pragma unroll
            for (int mt = 0; mt < 4; mt++) {
                uint32_t roff = (uint32_t)(a_row + mt * 16) * 128;
                uint32_t coff = (uint32_t)(s * 32 + a_cb) ^ xm;
                uint32_t a0, a1, a2, a3;
                ldsm_x4(ah_u + roff + coff, a0, a1, a2, a3);
#pragma unroll
                for (int nt = 0; nt < 4; nt++) {
                    uint32_t hb0 = bhf[(nt >> 1) * 4 + (nt & 1) * 2];
                    uint32_t hb1 = bhf[(nt >> 1) * 4 + (nt & 1) * 2 + 1];
                    mma_f16(acc[mt][nt], a0, a1, a2, a3, hb0, hb1);
                }
            }
        }
        __syncthreads();
    }

    {
        int g = lid >> 2, tig = lid & 3;
        int base_row = mb * GBM + warp_m + g;
        int base_col = nb * GBN + warp_n + tig * 2;
#pragma unroll
        for (int mt = 0; mt < 4; mt++) {
#pragma unroll
            for (int nt = 0; nt < 4; nt++) {
                int col = base_col + nt * 8;
                float2 bb = *(const float2*)(bias + col);
#pragma unroll
                for (int hrow = 0; hrow < 2; hrow++) {
                    int row = base_row + mt * 16 + hrow * 8;
                    float2 o;
                    o.x = acc[mt][nt][hrow * 2 + 0] + bb.x;
                    o.y = acc[mt][nt][hrow * 2 + 1] + bb.y;
                    if (RES) {
                        float2 r2 = *(const float2*)(res + (size_t)row * N + col);
                        o.x += r2.x; o.y += r2.y;
                    }
                    if (RELU) {
                        o.x = fmaxf(o.x, 0.f);
                        o.y = fmaxf(o.y, 0.f);
                    }
                    if (OUT == 0) {
                        *(float2*)(Cf + (size_t)row * N + col) = o;
                    } else {
                        __half2 hv = __floats2half2_rn(o.x, o.y);
                        *(__half2*)(Ch + (size_t)row * N + col) = hv;
                    }
                }
            }
        }
    }
}

// ---------------- fused QKV GEMM (M64, double-buffered) --------------------
// K section (sect==1): 3-term + hi/lo output. Q/V: 2-term, fp16 output.
__global__ void __launch_bounds__(256, 2) tc_qkv_gemm(
    const __half* __restrict__ Ah, const __half* __restrict__ Al,
    const __half* __restrict__ Bh, const __half* __restrict__ Bl,
    const float* __restrict__ bq, const float* __restrict__ bk,
    const float* __restrict__ bv,
    __half* __restrict__ Qh,
    __half* __restrict__ Kh, __half* __restrict__ Kl,
    __half* __restrict__ Vh)
{
    extern __shared__ char sm[];
    constexpr uint32_t AH_OFF = 0;
    constexpr uint32_t AL_OFF = 8192u;
    constexpr uint32_t BH_OFF = 16384u;
    constexpr uint32_t BL_OFF = 32768u;
    const uint32_t STAGE = 49152u;
    const int K = DM;

    const int tid = threadIdx.x;
    const int wid = tid >> 5;
    const int lid = tid & 31;
    const int nb = blockIdx.x, mb = blockIdx.y;
    const int sect = nb >> 3;
    const bool three_term = (sect == 1);

    const int warp_m = (wid >> 2) * 32;
    const int warp_n = (wid & 3) * 32;

    const uint32_t smb = smem_u32(sm);

    const int a_row = warp_m + (lid & 15);
    const uint32_t a_cb = (uint32_t)((lid >> 4) * 16);
    const int b_row_off = ((lid & 16) >> 1) + (lid & 7);
    const uint32_t b_cb = (lid & 8) ? 16u : 0u;
    const uint32_t xm = (uint32_t)((lid & 7) << 4);

    float acc[2][4][4];
#pragma unroll
    for (int i = 0; i < 2; i++)
#pragma unroll
        for (int j = 0; j < 4; j++)
#pragma unroll
            for (int r = 0; r < 4; r++) acc[i][j][r] = 0.f;

    const int sj = tid & 7;
    const int sr0 = tid >> 3;
    const int niter = K / GBK;

    auto stage = [&](int kt, int buf) {
        uint32_t base = smb + (uint32_t)buf * STAGE;
#pragma unroll
        for (int i = 0; i < 2; i++) {
            int r = i * 32 + sr0;
            uint32_t sw = (uint32_t)(r * 128 + ((sj * 16) ^ ((r & 7) << 4)));
            CP_ASYNC16(base + AH_OFF + sw, Ah + (size_t)(mb * 64 + r) * K + kt * GBK + sj * 8);
            if (three_term)
                CP_ASYNC16(base + AL_OFF + sw, Al + (size_t)(mb * 64 + r) * K + kt * GBK + sj * 8);
        }
#pragma unroll
        for (int i = 0; i < 4; i++) {
            int r = i * 32 + sr0;
            uint32_t sw = (uint32_t)(r * 128 + ((sj * 16) ^ ((r & 7) << 4)));
            CP_ASYNC16(base + BH_OFF + sw, Bh + (size_t)(nb * GBN + r) * K + kt * GBK + sj * 8);
            CP_ASYNC16(base + BL_OFF + sw, Bl + (size_t)(nb * GBN + r) * K + kt * GBK + sj * 8);
        }
    };

    stage(0, 0);
    CP_COMMIT();

    for (int kt = 0; kt < niter; kt++) {
        int buf = kt & 1;
        CP_WAIT0();
        __syncthreads();
        if (kt + 1 < niter) {
            stage(kt + 1, buf ^ 1);
            CP_COMMIT();
        }

        uint32_t ah_u = smb + (uint32_t)buf * STAGE + AH_OFF;
        uint32_t al_u = smb + (uint32_t)buf * STAGE + AL_OFF;
        uint32_t bh_u = smb + (uint32_t)buf * STAGE + BH_OFF;
        uint32_t bl_u = smb + (uint32_t)buf * STAGE + BL_OFF;

#pragma unroll
        for (int s = 0; s < 4; s++) {
            uint32_t bhf[8], blf[8];
#pragma unroll
            for (int pr = 0; pr < 2; pr++) {
                uint32_t roff = (uint32_t)(warp_n + pr * 16 + b_row_off) * 128;
                uint32_t coff = (uint32_t)(s * 32 + b_cb) ^ xm;
                ldsm_x4(bh_u + roff + coff, bhf[pr*4+0], bhf[pr*4+1], bhf[pr*4+2], bhf[pr*4+3]);
                ldsm_x4(bl_u + roff + coff, blf[pr*4+0], blf[pr*4+1], blf[pr*4+2], blf[pr*4+3]);
            }
#pragma unroll
            for (int mt = 0; mt < 2; mt++) {
                uint32_t roff = (uint32_t)(a_row + mt * 16) * 128;
                uint32_t coff = (uint32_t)(s * 32 + a_cb) ^ xm;
                uint32_t a0, a1, a2, a3, l0, l1, l2, l3;
                ldsm_x4(ah_u + roff + coff, a0, a1, a2, a3);
                if (three_term)
                    ldsm_x4(al_u + roff + coff, l0, l1, l2, l3);
#pragma unroll
                for (int nt = 0; nt < 4; nt++) {
                    uint32_t hb0 = bhf[(nt >> 1) * 4 + (nt & 1) * 2];
                    uint32_t hb1 = bhf[(nt >> 1) * 4 + (nt & 1) * 2 + 1];
                    uint32_t lb0 = blf[(nt >> 1) * 4 + (nt & 1) * 2];
                    uint32_t lb1 = blf[(nt >> 1) * 4 + (nt & 1) * 2 + 1];
                    mma_f16(acc[mt][nt], a0, a1, a2, a3, hb0, hb1);
                    mma_f16(acc[mt][nt], a0, a1, a2, a3, lb0, lb1);
                    if (three_term)
                        mma_f16(acc[mt][nt], l0, l1, l2, l3, hb0, hb1);
                }
            }
        }
        __syncthreads();
    }

    {
        int nb_l = nb & 7;
        const float* bp = (sect == 0) ? bq : ((sect == 1) ? bk : bv);
        __half* Dh = (sect == 0) ? Qh : ((sect == 1) ? Kh : Vh);

        int g = lid >> 2, tig = lid & 3;
        int base_row = mb * 64 + warp_m + g;
        int base_col = nb_l * GBN + warp_n + tig * 2;
#pragma unroll
        for (int mt = 0; mt < 2; mt++) {
#pragma unroll
            for (int nt = 0; nt < 4; nt++) {
                int col = base_col + nt * 8;
                float2 bb = *(const float2*)(bp + col);
#pragma unroll
                for (int hrow = 0; hrow < 2; hrow++) {
                    int row = base_row + mt * 16 + hrow * 8;
                    float ox = acc[mt][nt][hrow * 2 + 0] + bb.x;
                    float oy = acc[mt][nt][hrow * 2 + 1] + bb.y;
                    __half2 hv = __floats2half2_rn(ox, oy);
                    *(__half2*)(Dh + (size_t)row * DM + col) = hv;
                    if (three_term) {
                        float2 hf = __half22float2(hv);
                        __half2 lv = __floats2half2_rn(ox - hf.x, oy - hf.y);
                        *(__half2*)(Kl + (size_t)row * DM + col) = lv;
                    }
                }
            }
        }
    }
}

// ---------------- HMMA flash attention (Q fp16, K hi/lo, 2-term QK) -------
#define AQH 0u
#define ABUF0 16384u
#define ABUFSZ 24576u
#define APB 65536u
#define ATTN_SMEM 81920

__global__ void __launch_bounds__(256, 2) fattn_mma(
    const __half* __restrict__ Qh,
    const __half* __restrict__ Kh, const __half* __restrict__ Kl,
    const __half* __restrict__ Vh, __half* __restrict__ Oh)
{
    extern __shared__ char sm[];
    const uint32_t smb = smem_u32(sm);

    const int tid = threadIdx.x;
    const int wid = tid >> 5;
    const int lid = tid & 31;
    const int h = blockIdx.y, b = blockIdx.z;
    const int q0 = blockIdx.x * 128;

    const int warp_m = wid * 16;

    const int a_row = warp_m + (lid & 15);
    const uint32_t a_cb = (uint32_t)((lid >> 4) * 16);
    const int b_row_off = ((lid & 16) >> 1) + (lid & 7);
    const uint32_t b_cb = (lid & 8) ? 16u : 0u;
    const uint32_t xm = (uint32_t)((lid & 7) << 4);

    const int v_krow = lid & 15;
    const uint32_t v_db = (uint32_t)((lid >> 4) << 4);

    const size_t bh_off = ((size_t)b * S_LEN) * DM + h * DKH;

    const int sj = tid & 7;
    const int sr0 = tid >> 3;

    {
#pragma unroll
        for (int i = 0; i < 4; i++) {
            int r = sr0 + i * 32;
            uint32_t sw = (uint32_t)(r * 128 + ((sj * 16) ^ ((r & 7) << 4)));
            CP_ASYNC16(smb + AQH + sw, Qh + bh_off + (size_t)(q0 + r) * DM + sj * 8);
        }
        CP_COMMIT();
    }

    auto stage_kv = [&](int k0, int buf) {
        uint32_t base = smb + ABUF0 + (uint32_t)buf * ABUFSZ;
#pragma unroll
        for (int i = 0; i < 2; i++) {
            int r = sr0 + i * 32;
            uint32_t sw = (uint32_t)(r * 128 + ((sj * 16) ^ ((r & 7) << 4)));
            CP_ASYNC16(base + sw,          Kh + bh_off + (size_t)(k0 + r) * DM + sj * 8);
            CP_ASYNC16(base + 8192u + sw,  Kl + bh_off + (size_t)(k0 + r) * DM + sj * 8);
            CP_ASYNC16(base + 16384u + sw, Vh + bh_off + (size_t)(k0 + r) * DM + sj * 8);
        }
    };

    stage_kv(0, 0);
    CP_COMMIT();

    float Oa[8][4];
    float mrow[2], lrow[2];
#pragma unroll
    for (int nt = 0; nt < 8; nt++)
#pragma unroll
        for (int r = 0; r < 4; r++) Oa[nt][r] = 0.f;
    mrow[0] = mrow[1] = -INFINITY;
    lrow[0] = lrow[1] = 0.f;

    CP_WAIT0();
    __syncthreads();

    const int NT = S_LEN / 64;
    for (int t = 0; t < NT; t++) {
        int buf = t & 1;
        uint32_t kh_u = smb + ABUF0 + (uint32_t)buf * ABUFSZ;
        uint32_t kl_u = kh_u + 8192u;
        uint32_t vs_u = kh_u + 16384u;

        if (t + 1 < NT) {
            stage_kv((t + 1) * 64, buf ^ 1);
            CP_COMMIT();
        }

        // ---- phase A: S = Q (Kh + Kl)^T (2-term) ----
        float sacc[8][4];
#pragma unroll
        for (int nt = 0; nt < 8; nt++)
#pragma unroll
            for (int r = 0; r < 4; r++) sacc[nt][r] = 0.f;

#pragma unroll
        for (int s = 0; s < 4; s++) {
            uint32_t acoff = (uint32_t)(s * 32 + a_cb) ^ xm;
            uint32_t qa0, qa1, qa2, qa3;
            ldsm_x4(smb + AQH + (uint32_t)a_row * 128 + acoff, qa0, qa1, qa2, qa3);
            uint32_t bcoff = (uint32_t)(s * 32 + b_cb) ^ xm;
#pragma unroll
            for (int pr = 0; pr < 4; pr++) {
                uint32_t roff = (uint32_t)(pr * 16 + b_row_off) * 128;
                uint32_t h0, h1, h2, h3, l0, l1, l2, l3;
                ldsm_x4(kh_u + roff + bcoff, h0, h1, h2, h3);
                ldsm_x4(kl_u + roff + bcoff, l0, l1, l2, l3);
                mma_f16(sacc[pr*2+0], qa0, qa1, qa2, qa3, h0, h1);
                mma_f16(sacc[pr*2+0], qa0, qa1, qa2, qa3, l0, l1);
                mma_f16(sacc[pr*2+1], qa0, qa1, qa2, qa3, h2, h3);
                mma_f16(sacc[pr*2+1], qa0, qa1, qa2, qa3, l2, l3);
            }
        }

        // ---- online softmax on fragments ----
        float corr0, corr1;
#pragma unroll
        for (int r = 0; r < 2; r++) {
            float mx = -INFINITY;
#pragma unroll
            for (int nt = 0; nt < 8; nt++) {
                mx = fmaxf(mx, sacc[nt][r*2+0]);
                mx = fmaxf(mx, sacc[nt][r*2+1]);
            }
            mx = fmaxf(mx, __shfl_xor_sync(0xffffffffu, mx, 1));
            mx = fmaxf(mx, __shfl_xor_sync(0xffffffffu, mx, 2));
            float mn = fmaxf(mrow[r], mx);
            float c = __expf(mrow[r] - mn);
            mrow[r] = mn;
            float sum = 0.f;
#pragma unroll
            for (int nt = 0; nt < 8; nt++) {
                float e0 = __expf(sacc[nt][r*2+0] - mn);
                float e1 = __expf(sacc[nt][r*2+1] - mn);
                sacc[nt][r*2+0] = e0;
                sacc[nt][r*2+1] = e1;
                sum += e0 + e1;
            }
            sum += __shfl_xor_sync(0xffffffffu, sum, 1);
            sum += __shfl_xor_sync(0xffffffffu, sum, 2);
            lrow[r] = lrow[r] * c + sum;
            if (r == 0) corr0 = c; else corr1 = c;
        }
#pragma unroll
        for (int nt = 0; nt < 8; nt++) {
            Oa[nt][0] *= corr0; Oa[nt][1] *= corr0;
            Oa[nt][2] *= corr1; Oa[nt][3] *= corr1;
        }

        // ---- store P fp16 (warp-local rows) ----
        __syncwarp();
        {
            int g = lid >> 2, tig = lid & 3;
            int row0 = warp_m + g;
            int row1 = row0 + 8;
            uint32_t x0 = (uint32_t)((row0 & 7) << 4);
            uint32_t x1 = (uint32_t)((row1 & 7) << 4);
#pragma unroll
            for (int nt = 0; nt < 8; nt++) {
                int col = tig * 2 + nt * 8;
                __half2 p0 = __floats2half2_rn(sacc[nt][0], sacc[nt][1]);
                __half2 p1 = __floats2half2_rn(sacc[nt][2], sacc[nt][3]);
                *(__half2*)(sm + APB + (uint32_t)(row0 * 128 + ((col * 2) ^ x0))) = p0;
                *(__half2*)(sm + APB + (uint32_t)(row1 * 128 + ((col * 2) ^ x1))) = p1;
            }
        }
        __syncwarp();

        // ---- phase B: O += P @ V ----
#pragma unroll
        for (int s = 0; s < 4; s++) {
            uint32_t acoff = (uint32_t)(s * 32 + a_cb) ^ xm;
            uint32_t pa0, pa1, pa2, pa3;
            ldsm_x4(smb + APB + (uint32_t)a_row * 128 + acoff, pa0, pa1, pa2, pa3);
            int krow = s * 16 + v_krow;
#pragma unroll
            for (int pr = 0; pr < 4; pr++) {
                uint32_t vaddr = vs_u + (uint32_t)krow * 128 +
                                 (((uint32_t)(pr * 32) + v_db) ^ ((uint32_t)(krow & 7) << 4));
                uint32_t v0, v1, v2, v3;
                ldsm_x4_t(vaddr, v0, v1, v2, v3);
                mma_f16(Oa[pr*2+0], pa0, pa1, pa2, pa3, v0, v1);
                mma_f16(Oa[pr*2+1], pa0, pa1, pa2, pa3, v2, v3);
            }
        }

        if (t + 1 < NT) CP_WAIT0();
        __syncthreads();
    }

    {
        int g = lid >> 2, tig = lid & 3;
        float inv0 = 1.0f / lrow[0];
        float inv1 = 1.0f / lrow[1];
        int row0 = q0 + warp_m + g;
        int row1 = row0 + 8;
#pragma unroll
        for (int nt = 0; nt < 8; nt++) {
            int col = tig * 2 + nt * 8;
            __half2 o0 = __floats2half2_rn(Oa[nt][0] * inv0, Oa[nt][1] * inv0);
            __half2 o1 = __floats2half2_rn(Oa[nt][2] * inv1, Oa[nt][3] * inv1);
            *(__half2*)(Oh + bh_off + (size_t)row0 * DM + col) = o0;
            *(__half2*)(Oh + bh_off + (size_t)row1 * DM + col) = o1;
        }
    }
}

// ---------------- launch ----------------
extern "C" void kernel_launch(void* const* d_in, const int* in_sizes, int n_in,
                              void* d_out, int out_size)
{
    const float* x    = (const float*)d_in[0];
    const float* Wq   = (const float*)d_in[1];
    const float* bq   = (const float*)d_in[2];
    const float* Wk   = (const float*)d_in[3];
    const float* bk   = (const float*)d_in[4];
    const float* Wv   = (const float*)d_in[5];
    const float* bv   = (const float*)d_in[6];
    const float* Wo   = (const float*)d_in[7];
    const float* bo   = (const float*)d_in[8];
    const float* W1   = (const float*)d_in[9];
    const float* b1   = (const float*)d_in[10];
    const float* W2   = (const float*)d_in[11];
    const float* b2   = (const float*)d_in[12];
    const float* ln1a = (const float*)d_in[13];
    const float* ln1b = (const float*)d_in[14];
    const float* ln2a = (const float*)d_in[15];
    const float* ln2b = (const float*)d_in[16];
    float* out = (float*)d_out;

    __half *p_n1h, *p_n1l, *p_qh, *p_kh, *p_kl, *p_vh;
    __half *p_aoh, *p_n2h, *p_n2l, *p_f1h;
    float *p_h;
    __half *wqkvh, *wqkvl, *woh, *w1h, *w2h;
    cudaGetSymbolAddress((void**)&p_n1h, g_n1h);
    cudaGetSymbolAddress((void**)&p_n1l, g_n1l);
    cudaGetSymbolAddress((void**)&p_qh, g_qh);
    cudaGetSymbolAddress((void**)&p_kh, g_kh);
    cudaGetSymbolAddress((void**)&p_kl, g_kl);
    cudaGetSymbolAddress((void**)&p_vh, g_vh);
    cudaGetSymbolAddress((void**)&p_aoh, g_aoh);
    cudaGetSymbolAddress((void**)&p_h,  g_h);
    cudaGetSymbolAddress((void**)&p_n2h, g_n2h);
    cudaGetSymbolAddress((void**)&p_n2l, g_n2l);
    cudaGetSymbolAddress((void**)&p_f1h, g_f1h);
    cudaGetSymbolAddress((void**)&wqkvh, g_wqkvh);
    cudaGetSymbolAddress((void**)&wqkvl, g_wqkvl);
    cudaGetSymbolAddress((void**)&woh, g_woh);
    cudaGetSymbolAddress((void**)&w1h, g_w1h);
    cudaGetSymbolAddress((void**)&w2h, g_w2h);

    const int SMEM1 = 2 * 2 * 16384;   // 64KB
    const int SMEMQ = 2 * 49152;       // 96KB

    cudaFuncSetAttribute(fattn_mma,
                         cudaFuncAttributeMaxDynamicSharedMemorySize, ATTN_SMEM);
    cudaFuncSetAttribute(tc_qkv_gemm,
                         cudaFuncAttributeMaxDynamicSharedMemorySize, SMEMQ);
    cudaFuncSetAttribute(tc2_gemm<false, true, 0>,
                         cudaFuncAttributeMaxDynamicSharedMemorySize, SMEM1);
    cudaFuncSetAttribute(tc2_gemm<true, false, 1>,
                         cudaFuncAttributeMaxDynamicSharedMemorySize, SMEM1);

    // 0) weight transpose + split (lo only for K)
    wsplit4_kernel<<<dim3(DM / 32, DM / 32, 4), 256>>>(
        Wq, Wk, Wv, Wo, wqkvh, wqkvl, woh);
    wsplit_kernel<<<dim3(DFF / 32, DM / 32), 256>>>(W1, w1h, DM, DFF);
    wsplit_kernel<<<dim3(DM / 32, DFF / 32), 256>>>(W2, w2h, DFF, DM);

    // 1) LN1 -> fp16 hi/lo
    ln_kernel<<<NTOK, 256>>>(x, ln1a, ln1b, p_n1h, p_n1l);

    // 2) fused QKV projection (K: 3-term + hi/lo; Q/V: 2-term fp16)
    tc_qkv_gemm<<<dim3(3 * DM / GBN, NTOK / 64), 256, SMEMQ>>>(
        p_n1h, p_n1l, wqkvh, wqkvl, bq, bk, bv,
        p_qh, p_kh, p_kl, p_vh);

    // 3) HMMA flash attention (2-term QK; no 1/sqrt(dk) scaling)
    fattn_mma<<<dim3(S_LEN / 128, NHEAD, BATCH), 256, ATTN_SMEM>>>(
        p_qh, p_kh, p_kl, p_vh, p_aoh);

    // 4) output projection + residual(x) -> h fp32 (1-term)
    dim3 gP(DM / GBN, NTOK / GBM);
    tc2_gemm<false, true, 0><<<gP, 256, SMEM1>>>(
        p_aoh, woh, bo, x, p_h, nullptr, NTOK, DM, DM);

    // 5) LN2 -> fp16
    ln_kernel<<<NTOK, 256>>>(p_h, ln2a, ln2b, p_n2h, p_n2l);

    // 6) FFN up + ReLU -> f1 fp16 (1-term)
    tc2_gemm<true, false, 1><<<dim3(DFF / GBN, NTOK / GBM), 256, SMEM1>>>(
        p_n2h, w1h, b1, nullptr, nullptr, p_f1h, NTOK, DFF, DM);

    // 7) FFN down + residual(h) -> out fp32 (1-term)
    tc2_gemm<false, true, 0><<<dim3(DM / GBN, NTOK / GBM), 256, SMEM1>>>(
        p_f1h, w2h, b2, p_h, out, nullptr, NTOK, DM, DFF);
}

// round 16
// speedup vs baseline: 2.0176x; 1.3078x over previous
#include <cuda_runtime.h>
#include <cuda_fp16.h>
#include <math.h>
#include <cstdint>

#define S_LEN 2048
#define BATCH 2
#define DM    1024
#define NHEAD 16
#define DKH   64
#define DFF   4096
#define NTOK  (BATCH * S_LEN)   // 4096
#define LN_EPS 1e-6f

#define GBM 128
#define GBN 128
#define GBK 64

__device__ __forceinline__ uint32_t smem_u32(const void* p) {
    uint32_t a;
    asm("{ .reg .u64 t; cvta.to.shared.u64 t, %1; cvt.u32.u64 %0, t; }"
        : "=r"(a) : "l"(p));
    return a;
}
__device__ __forceinline__ void ldsm_x4(uint32_t addr, uint32_t& r0, uint32_t& r1,
                                        uint32_t& r2, uint32_t& r3) {
    asm volatile("ldmatrix.sync.aligned.m8n8.x4.shared.b16 {%0,%1,%2,%3}, [%4];"
                 : "=r"(r0), "=r"(r1), "=r"(r2), "=r"(r3) : "r"(addr));
}
__device__ __forceinline__ void ldsm_x4_t(uint32_t addr, uint32_t& r0, uint32_t& r1,
                                          uint32_t& r2, uint32_t& r3) {
    asm volatile("ldmatrix.sync.aligned.m8n8.x4.trans.shared.b16 {%0,%1,%2,%3}, [%4];"
                 : "=r"(r0), "=r"(r1), "=r"(r2), "=r"(r3) : "r"(addr));
}
__device__ __forceinline__ void mma_f16(float* c, uint32_t a0, uint32_t a1,
                                        uint32_t a2, uint32_t a3,
                                        uint32_t b0, uint32_t b1) {
    asm volatile(
        "mma.sync.aligned.m16n8k16.row.col.f32.f16.f16.f32 "
        "{%0,%1,%2,%3}, {%4,%5,%6,%7}, {%8,%9}, {%0,%1,%2,%3};"
        : "+f"(c[0]), "+f"(c[1]), "+f"(c[2]), "+f"(c[3])
        : "r"(a0), "r"(a1), "r"(a2), "r"(a3), "r"(b0), "r"(b1));
}
#define CP_ASYNC16(dst, src) \
    asm volatile("cp.async.cg.shared.global [%0], [%1], 16;" :: "r"(dst), "l"(src))
#define CP_COMMIT() asm volatile("cp.async.commit_group;" ::: "memory")
#define CP_WAIT0()  asm volatile("cp.async.wait_group 0;" ::: "memory")

// ---------------- scratch (device globals; no allocation) ----------------
__device__ __half g_n1h[NTOK * DM];
__device__ __half g_qh[NTOK * DM];
__device__ __half g_kh[NTOK * DM];
__device__ __half g_vh[NTOK * DM];
__device__ __half g_aoh[NTOK * DM];
__device__ float  g_h [NTOK * DM];
__device__ __half g_n2h[NTOK * DM];
__device__ __half g_f1h[NTOK * DFF];
__device__ __half g_wqkvh[3 * DM * DM];
__device__ __half g_woh[DM * DM];
__device__ __half g_w1h[DM * DFF];
__device__ __half g_w2h[DFF * DM];

// ---------------- weight transpose -> fp16 ---------------------------------
__global__ void __launch_bounds__(256) wsplit_kernel(
    const float* __restrict__ W, __half* __restrict__ Bh, int K, int N)
{
    __shared__ float tile[32][33];
    int n0 = blockIdx.x * 32, k0 = blockIdx.y * 32;
    int tx = threadIdx.x & 31, ty = threadIdx.x >> 5;
#pragma unroll
    for (int i = 0; i < 4; i++)
        tile[ty + 8 * i][tx] = W[(size_t)(k0 + ty + 8 * i) * N + n0 + tx];
    __syncthreads();
#pragma unroll
    for (int i = 0; i < 4; i++) {
        int nl = ty + 8 * i;
        Bh[(size_t)(n0 + nl) * K + k0 + tx] = __float2half_rn(tile[tx][nl]);
    }
}

// 4 square 1024x1024 weights in one launch, fp16 only
__global__ void __launch_bounds__(256) wsplit4_kernel(
    const float* __restrict__ Wq, const float* __restrict__ Wk,
    const float* __restrict__ Wv, const float* __restrict__ Wo,
    __half* __restrict__ qkvh, __half* __restrict__ woh)
{
    __shared__ float tile[32][33];
    int z = blockIdx.z;
    const float* W = (z == 0) ? Wq : (z == 1) ? Wk : (z == 2) ? Wv : Wo;
    __half* Bh = (z < 3) ? (qkvh + (size_t)z * DM * DM) : woh;
    int n0 = blockIdx.x * 32, k0 = blockIdx.y * 32;
    int tx = threadIdx.x & 31, ty = threadIdx.x >> 5;
#pragma unroll
    for (int i = 0; i < 4; i++)
        tile[ty + 8 * i][tx] = W[(size_t)(k0 + ty + 8 * i) * DM + n0 + tx];
    __syncthreads();
#pragma unroll
    for (int i = 0; i < 4; i++) {
        int nl = ty + 8 * i;
        Bh[(size_t)(n0 + nl) * DM + k0 + tx] = __float2half_rn(tile[tx][nl]);
    }
}

// ---------------- LayerNorm -> fp16 ----------------------------------------
__global__ void __launch_bounds__(256) ln_kernel(
    const float* __restrict__ x, const float* __restrict__ alpha,
    const float* __restrict__ beta, __half* __restrict__ yh)
{
    int row = blockIdx.x;
    int tid = threadIdx.x;
    const float4* x4 = (const float4*)(x + (size_t)row * DM);
    float4 v = x4[tid];
    float s = v.x + v.y + v.z + v.w;
    float q = v.x * v.x + v.y * v.y + v.z * v.z + v.w * v.w;

    __shared__ float rs[8], rq[8];
#pragma unroll
    for (int o = 16; o; o >>= 1) {
        s += __shfl_xor_sync(0xffffffffu, s, o);
        q += __shfl_xor_sync(0xffffffffu, q, o);
    }
    if ((tid & 31) == 0) { rs[tid >> 5] = s; rq[tid >> 5] = q; }
    __syncthreads();
    s = 0.f; q = 0.f;
#pragma unroll
    for (int i = 0; i < 8; i++) { s += rs[i]; q += rq[i]; }

    float mean = s * (1.0f / DM);
    float var  = (q - (float)DM * mean * mean) * (1.0f / (DM - 1));
    float a    = alpha[0];
    float b    = beta[0];
    float inv  = a / (sqrtf(var) + LN_EPS);

    float o0 = (v.x - mean) * inv + b;
    float o1 = (v.y - mean) * inv + b;
    float o2 = (v.z - mean) * inv + b;
    float o3 = (v.w - mean) * inv + b;

    __half2 h0 = __floats2half2_rn(o0, o1);
    __half2 h1 = __floats2half2_rn(o2, o3);
    uint2 uh;
    uh.x = *(uint32_t*)&h0; uh.y = *(uint32_t*)&h1;
    *(uint2*)(yh + (size_t)row * DM + tid * 4) = uh;
}

// ---------------- 1-term HMMA GEMM (Wo / FFN) ------------------------------
template<bool RELU, bool RES, int OUT>
__global__ void __launch_bounds__(256, 2) tc2_gemm(
    const __half* __restrict__ Ah, const __half* __restrict__ Bh,
    const float* __restrict__ bias, const float* __restrict__ res,
    float* __restrict__ Cf, __half* __restrict__ Ch,
    int M, int N, int K)
{
    extern __shared__ char sm[];
    constexpr uint32_t AH_OFF = 0;
    constexpr uint32_t BH_OFF = 16384u;
    constexpr uint32_t STAGE = 32768u;

    const int tid = threadIdx.x;
    const int wid = tid >> 5;
    const int lid = tid & 31;
    const int nb = blockIdx.x, mb = blockIdx.y;

    const int warp_m = (wid >> 2) * 64;
    const int warp_n = (wid & 3) * 32;

    const uint32_t smb = smem_u32(sm);

    const int a_row = warp_m + (lid & 15);
    const uint32_t a_cb = (uint32_t)((lid >> 4) * 16);
    const int b_row_off = ((lid & 16) >> 1) + (lid & 7);
    const uint32_t b_cb = (lid & 8) ? 16u : 0u;
    const uint32_t xm = (uint32_t)((lid & 7) << 4);

    float acc[4][4][4];
#pragma unroll
    for (int i = 0; i < 4; i++)
#pragma unroll
        for (int j = 0; j < 4; j++)
#pragma unroll
            for (int r = 0; r < 4; r++) acc[i][j][r] = 0.f;

    const int sj = tid & 7;
    const int sr0 = tid >> 3;
    const int niter = K / GBK;

    auto stage = [&](int kt, int buf) {
        uint32_t base = smb + (uint32_t)buf * STAGE;
#pragma unroll
        for (int i = 0; i < 4; i++) {
            int r = i * 32 + sr0;
            uint32_t sw = (uint32_t)(r * 128 + ((sj * 16) ^ ((r & 7) << 4)));
            CP_ASYNC16(base + AH_OFF + sw, Ah + (size_t)(mb * GBM + r) * K + kt * GBK + sj * 8);
            CP_ASYNC16(base + BH_OFF + sw, Bh + (size_t)(nb * GBN + r) * K + kt * GBK + sj * 8);
        }
    };

    stage(0, 0);
    CP_COMMIT();

    for (int kt = 0; kt < niter; kt++) {
        int buf = kt & 1;
        CP_WAIT0();
        __syncthreads();
        if (kt + 1 < niter) {
            stage(kt + 1, buf ^ 1);
            CP_COMMIT();
        }

        uint32_t ah_u = smb + (uint32_t)buf * STAGE + AH_OFF;
        uint32_t bh_u = smb + (uint32_t)buf * STAGE + BH_OFF;

#pragma unroll
        for (int s = 0; s < 4; s++) {
            uint32_t bhf[8];
#pragma unroll
            for (int pr = 0; pr < 2; pr++) {
                uint32_t roff = (uint32_t)(warp_n + pr * 16 + b_row_off) * 128;
                uint32_t coff = (uint32_t)(s * 32 + b_cb) ^ xm;
                ldsm_x4(bh_u + roff + coff, bhf[pr*4+0], bhf[pr*4+1], bhf[pr*4+2], bhf[pr*4+3]);
            }
#pragma unroll
            for (int mt = 0; mt < 4; mt++) {
                uint32_t roff = (uint32_t)(a_row + mt * 16) * 128;
                uint32_t coff = (uint32_t)(s * 32 + a_cb) ^ xm;
                uint32_t a0, a1, a2, a3;
                ldsm_x4(ah_u + roff + coff, a0, a1, a2, a3);
#pragma unroll
                for (int nt = 0; nt < 4; nt++) {
                    uint32_t hb0 = bhf[(nt >> 1) * 4 + (nt & 1) * 2];
                    uint32_t hb1 = bhf[(nt >> 1) * 4 + (nt & 1) * 2 + 1];
                    mma_f16(acc[mt][nt], a0, a1, a2, a3, hb0, hb1);
                }
            }
        }
        __syncthreads();
    }

    {
        int g = lid >> 2, tig = lid & 3;
        int base_row = mb * GBM + warp_m + g;
        int base_col = nb * GBN + warp_n + tig * 2;
#pragma unroll
        for (int mt = 0; mt < 4; mt++) {
#pragma unroll
            for (int nt = 0; nt < 4; nt++) {
                int col = base_col + nt * 8;
                float2 bb = *(const float2*)(bias + col);
#pragma unroll
                for (int hrow = 0; hrow < 2; hrow++) {
                    int row = base_row + mt * 16 + hrow * 8;
                    float2 o;
                    o.x = acc[mt][nt][hrow * 2 + 0] + bb.x;
                    o.y = acc[mt][nt][hrow * 2 + 1] + bb.y;
                    if (RES) {
                        float2 r2 = *(const float2*)(res + (size_t)row * N + col);
                        o.x += r2.x; o.y += r2.y;
                    }
                    if (RELU) {
                        o.x = fmaxf(o.x, 0.f);
                        o.y = fmaxf(o.y, 0.f);
                    }
                    if (OUT == 0) {
                        *(float2*)(Cf + (size_t)row * N + col) = o;
                    } else {
                        __half2 hv = __floats2half2_rn(o.x, o.y);
                        *(__half2*)(Ch + (size_t)row * N + col) = hv;
                    }
                }
            }
        }
    }
}

// ---------------- fused QKV GEMM (M128, 1-term, routed epilogue) -----------
__global__ void __launch_bounds__(256, 2) tc_qkv_gemm(
    const __half* __restrict__ Ah, const __half* __restrict__ Bh,
    const float* __restrict__ bq, const float* __restrict__ bk,
    const float* __restrict__ bv,
    __half* __restrict__ Qh, __half* __restrict__ Kh, __half* __restrict__ Vh)
{
    extern __shared__ char sm[];
    constexpr uint32_t AH_OFF = 0;
    constexpr uint32_t BH_OFF = 16384u;
    constexpr uint32_t STAGE = 32768u;
    const int K = DM;

    const int tid = threadIdx.x;
    const int wid = tid >> 5;
    const int lid = tid & 31;
    const int nb = blockIdx.x, mb = blockIdx.y;

    const int warp_m = (wid >> 2) * 64;
    const int warp_n = (wid & 3) * 32;

    const uint32_t smb = smem_u32(sm);

    const int a_row = warp_m + (lid & 15);
    const uint32_t a_cb = (uint32_t)((lid >> 4) * 16);
    const int b_row_off = ((lid & 16) >> 1) + (lid & 7);
    const uint32_t b_cb = (lid & 8) ? 16u : 0u;
    const uint32_t xm = (uint32_t)((lid & 7) << 4);

    float acc[4][4][4];
#pragma unroll
    for (int i = 0; i < 4; i++)
#pragma unroll
        for (int j = 0; j < 4; j++)
#pragma unroll
            for (int r = 0; r < 4; r++) acc[i][j][r] = 0.f;

    const int sj = tid & 7;
    const int sr0 = tid >> 3;
    const int niter = K / GBK;

    auto stage = [&](int kt, int buf) {
        uint32_t base = smb + (uint32_t)buf * STAGE;
#pragma unroll
        for (int i = 0; i < 4; i++) {
            int r = i * 32 + sr0;
            uint32_t sw = (uint32_t)(r * 128 + ((sj * 16) ^ ((r & 7) << 4)));
            CP_ASYNC16(base + AH_OFF + sw, Ah + (size_t)(mb * GBM + r) * K + kt * GBK + sj * 8);
            CP_ASYNC16(base + BH_OFF + sw, Bh + (size_t)(nb * GBN + r) * K + kt * GBK + sj * 8);
        }
    };

    stage(0, 0);
    CP_COMMIT();

    for (int kt = 0; kt < niter; kt++) {
        int buf = kt & 1;
        CP_WAIT0();
        __syncthreads();
        if (kt + 1 < niter) {
            stage(kt + 1, buf ^ 1);
            CP_COMMIT();
        }

        uint32_t ah_u = smb + (uint32_t)buf * STAGE + AH_OFF;
        uint32_t bh_u = smb + (uint32_t)buf * STAGE + BH_OFF;

#pragma unroll
        for (int s = 0; s < 4; s++) {
            uint32_t bhf[8];
#pragma unroll
            for (int pr = 0; pr < 2; pr++) {
                uint32_t roff = (uint32_t)(warp_n + pr * 16 + b_row_off) * 128;
                uint32_t coff = (uint32_t)(s * 32 + b_cb) ^ xm;
                ldsm_x4(bh_u + roff + coff, bhf[pr*4+0], bhf[pr*4+1], bhf[pr*4+2], bhf[pr*4+3]);
            }
#pragma unroll
            for (int mt = 0; mt < 4; mt++) {
                uint32_t roff = (uint32_t)(a_row + mt * 16) * 128;
                uint32_t coff = (uint32_t)(s * 32 + a_cb) ^ xm;
                uint32_t a0, a1, a2, a3;
                ldsm_x4(ah_u + roff + coff, a0, a1, a2, a3);
#pragma unroll
                for (int nt = 0; nt < 4; nt++) {
                    uint32_t hb0 = bhf[(nt >> 1) * 4 + (nt & 1) * 2];
                    uint32_t hb1 = bhf[(nt >> 1) * 4 + (nt & 1) * 2 + 1];
                    mma_f16(acc[mt][nt], a0, a1, a2, a3, hb0, hb1);
                }
            }
        }
        __syncthreads();
    }

    {
        int sect = nb >> 3;                 // 0=Q, 1=K, 2=V
        int nb_l = nb & 7;
        const float* bp = (sect == 0) ? bq : ((sect == 1) ? bk : bv);
        __half* Dh = (sect == 0) ? Qh : ((sect == 1) ? Kh : Vh);

        int g = lid >> 2, tig = lid & 3;
        int base_row = mb * GBM + warp_m + g;
        int base_col = nb_l * GBN + warp_n + tig * 2;
#pragma unroll
        for (int mt = 0; mt < 4; mt++) {
#pragma unroll
            for (int nt = 0; nt < 4; nt++) {
                int col = base_col + nt * 8;
                float2 bb = *(const float2*)(bp + col);
#pragma unroll
                for (int hrow = 0; hrow < 2; hrow++) {
                    int row = base_row + mt * 16 + hrow * 8;
                    __half2 hv = __floats2half2_rn(acc[mt][nt][hrow * 2 + 0] + bb.x,
                                                   acc[mt][nt][hrow * 2 + 1] + bb.y);
                    *(__half2*)(Dh + (size_t)row * DM + col) = hv;
                }
            }
        }
    }
}

// ---------------- HMMA flash attention (pure fp16 operands) ----------------
#define AQH 0u
#define ABUF0 16384u
#define ABUFSZ 16384u
#define APB 49152u
#define ATTN_SMEM 65536

__global__ void __launch_bounds__(256, 2) fattn_mma(
    const __half* __restrict__ Qh, const __half* __restrict__ Kh,
    const __half* __restrict__ Vh, __half* __restrict__ Oh)
{
    extern __shared__ char sm[];
    const uint32_t smb = smem_u32(sm);

    const int tid = threadIdx.x;
    const int wid = tid >> 5;
    const int lid = tid & 31;
    const int h = blockIdx.y, b = blockIdx.z;
    const int q0 = blockIdx.x * 128;

    const int warp_m = wid * 16;

    const int a_row = warp_m + (lid & 15);
    const uint32_t a_cb = (uint32_t)((lid >> 4) * 16);
    const int b_row_off = ((lid & 16) >> 1) + (lid & 7);
    const uint32_t b_cb = (lid & 8) ? 16u : 0u;
    const uint32_t xm = (uint32_t)((lid & 7) << 4);

    const int v_krow = lid & 15;
    const uint32_t v_db = (uint32_t)((lid >> 4) << 4);

    const size_t bh_off = ((size_t)b * S_LEN) * DM + h * DKH;

    const int sj = tid & 7;
    const int sr0 = tid >> 3;

    {
#pragma unroll
        for (int i = 0; i < 4; i++) {
            int r = sr0 + i * 32;
            uint32_t sw = (uint32_t)(r * 128 + ((sj * 16) ^ ((r & 7) << 4)));
            CP_ASYNC16(smb + AQH + sw, Qh + bh_off + (size_t)(q0 + r) * DM + sj * 8);
        }
        CP_COMMIT();
    }

    auto stage_kv = [&](int k0, int buf) {
        uint32_t base = smb + ABUF0 + (uint32_t)buf * ABUFSZ;
#pragma unroll
        for (int i = 0; i < 2; i++) {
            int r = sr0 + i * 32;
            uint32_t sw = (uint32_t)(r * 128 + ((sj * 16) ^ ((r & 7) << 4)));
            CP_ASYNC16(base + sw,         Kh + bh_off + (size_t)(k0 + r) * DM + sj * 8);
            CP_ASYNC16(base + 8192u + sw, Vh + bh_off + (size_t)(k0 + r) * DM + sj * 8);
        }
    };

    stage_kv(0, 0);
    CP_COMMIT();

    float Oa[8][4];
    float mrow[2], lrow[2];
#pragma unroll
    for (int nt = 0; nt < 8; nt++)
#pragma unroll
        for (int r = 0; r < 4; r++) Oa[nt][r] = 0.f;
    mrow[0] = mrow[1] = -INFINITY;
    lrow[0] = lrow[1] = 0.f;

    CP_WAIT0();
    __syncthreads();

    const int NT = S_LEN / 64;
    for (int t = 0; t < NT; t++) {
        int buf = t & 1;
        uint32_t kh_u = smb + ABUF0 + (uint32_t)buf * ABUFSZ;
        uint32_t vs_u = kh_u + 8192u;

        if (t + 1 < NT) {
            stage_kv((t + 1) * 64, buf ^ 1);
            CP_COMMIT();
        }

        // ---- phase A: S = Q K^T (1-term fp16) ----
        float sacc[8][4];
#pragma unroll
        for (int nt = 0; nt < 8; nt++)
#pragma unroll
            for (int r = 0; r < 4; r++) sacc[nt][r] = 0.f;

#pragma unroll
        for (int s = 0; s < 4; s++) {
            uint32_t acoff = (uint32_t)(s * 32 + a_cb) ^ xm;
            uint32_t qa0, qa1, qa2, qa3;
            ldsm_x4(smb + AQH + (uint32_t)a_row * 128 + acoff, qa0, qa1, qa2, qa3);
            uint32_t bcoff = (uint32_t)(s * 32 + b_cb) ^ xm;
#pragma unroll
            for (int pr = 0; pr < 4; pr++) {
                uint32_t roff = (uint32_t)(pr * 16 + b_row_off) * 128;
                uint32_t h0, h1, h2, h3;
                ldsm_x4(kh_u + roff + bcoff, h0, h1, h2, h3);
                mma_f16(sacc[pr*2+0], qa0, qa1, qa2, qa3, h0, h1);
                mma_f16(sacc[pr*2+1], qa0, qa1, qa2, qa3, h2, h3);
            }
        }

        // ---- online softmax on fragments ----
        float corr0, corr1;
#pragma unroll
        for (int r = 0; r < 2; r++) {
            float mx = -INFINITY;
#pragma unroll
            for (int nt = 0; nt < 8; nt++) {
                mx = fmaxf(mx, sacc[nt][r*2+0]);
                mx = fmaxf(mx, sacc[nt][r*2+1]);
            }
            mx = fmaxf(mx, __shfl_xor_sync(0xffffffffu, mx, 1));
            mx = fmaxf(mx, __shfl_xor_sync(0xffffffffu, mx, 2));
            float mn = fmaxf(mrow[r], mx);
            float c = __expf(mrow[r] - mn);
            mrow[r] = mn;
            float sum = 0.f;
#pragma unroll
            for (int nt = 0; nt < 8; nt++) {
                float e0 = __expf(sacc[nt][r*2+0] - mn);
                float e1 = __expf(sacc[nt][r*2+1] - mn);
                sacc[nt][r*2+0] = e0;
                sacc[nt][r*2+1] = e1;
                sum += e0 + e1;
            }
            sum += __shfl_xor_sync(0xffffffffu, sum, 1);
            sum += __shfl_xor_sync(0xffffffffu, sum, 2);
            lrow[r] = lrow[r] * c + sum;
            if (r == 0) corr0 = c; else corr1 = c;
        }
#pragma unroll
        for (int nt = 0; nt < 8; nt++) {
            Oa[nt][0] *= corr0; Oa[nt][1] *= corr0;
            Oa[nt][2] *= corr1; Oa[nt][3] *= corr1;
        }

        // ---- store P fp16 (warp-local rows) ----
        __syncwarp();
        {
            int g = lid >> 2, tig = lid & 3;
            int row0 = warp_m + g;
            int row1 = row0 + 8;
            uint32_t x0 = (uint32_t)((row0 & 7) << 4);
            uint32_t x1 = (uint32_t)((row1 & 7) << 4);
#pragma unroll
            for (int nt = 0; nt < 8; nt++) {
                int col = tig * 2 + nt * 8;
                __half2 p0 = __floats2half2_rn(sacc[nt][0], sacc[nt][1]);
                __half2 p1 = __floats2half2_rn(sacc[nt][2], sacc[nt][3]);
                *(__half2*)(sm + APB + (uint32_t)(row0 * 128 + ((col * 2) ^ x0))) = p0;
                *(__half2*)(sm + APB + (uint32_t)(row1 * 128 + ((col * 2) ^ x1))) = p1;
            }
        }
        __syncwarp();

        // ---- phase B: O += P @ V ----
#pragma unroll
        for (int s = 0; s < 4; s++) {
            uint32_t acoff = (uint32_t)(s * 32 + a_cb) ^ xm;
            uint32_t pa0, pa1, pa2, pa3;
            ldsm_x4(smb + APB + (uint32_t)a_row * 128 + acoff, pa0, pa1, pa2, pa3);
            int krow = s * 16 + v_krow;
#pragma unroll
            for (int pr = 0; pr < 4; pr++) {
                uint32_t vaddr = vs_u + (uint32_t)krow * 128 +
                                 (((uint32_t)(pr * 32) + v_db) ^ ((uint32_t)(krow & 7) << 4));
                uint32_t v0, v1, v2, v3;
                ldsm_x4_t(vaddr, v0, v1, v2, v3);
                mma_f16(Oa[pr*2+0], pa0, pa1, pa2, pa3, v0, v1);
                mma_f16(Oa[pr*2+1], pa0, pa1, pa2, pa3, v2, v3);
            }
        }

        if (t + 1 < NT) CP_WAIT0();
        __syncthreads();
    }

    {
        int g = lid >> 2, tig = lid & 3;
        float inv0 = 1.0f / lrow[0];
        float inv1 = 1.0f / lrow[1];
        int row0 = q0 + warp_m + g;
        int row1 = row0 + 8;
#pragma unroll
        for (int nt = 0; nt < 8; nt++) {
            int col = tig * 2 + nt * 8;
            __half2 o0 = __floats2half2_rn(Oa[nt][0] * inv0, Oa[nt][1] * inv0);
            __half2 o1 = __floats2half2_rn(Oa[nt][2] * inv1, Oa[nt][3] * inv1);
            *(__half2*)(Oh + bh_off + (size_t)row0 * DM + col) = o0;
            *(__half2*)(Oh + bh_off + (size_t)row1 * DM + col) = o1;
        }
    }
}

// ---------------- launch ----------------
extern "C" void kernel_launch(void* const* d_in, const int* in_sizes, int n_in,
                              void* d_out, int out_size)
{
    const float* x    = (const float*)d_in[0];
    const float* Wq   = (const float*)d_in[1];
    const float* bq   = (const float*)d_in[2];
    const float* Wk   = (const float*)d_in[3];
    const float* bk   = (const float*)d_in[4];
    const float* Wv   = (const float*)d_in[5];
    const float* bv   = (const float*)d_in[6];
    const float* Wo   = (const float*)d_in[7];
    const float* bo   = (const float*)d_in[8];
    const float* W1   = (const float*)d_in[9];
    const float* b1   = (const float*)d_in[10];
    const float* W2   = (const float*)d_in[11];
    const float* b2   = (const float*)d_in[12];
    const float* ln1a = (const float*)d_in[13];
    const float* ln1b = (const float*)d_in[14];
    const float* ln2a = (const float*)d_in[15];
    const float* ln2b = (const float*)d_in[16];
    float* out = (float*)d_out;

    __half *p_n1h, *p_qh, *p_kh, *p_vh, *p_aoh, *p_n2h, *p_f1h;
    float *p_h;
    __half *wqkvh, *woh, *w1h, *w2h;
    cudaGetSymbolAddress((void**)&p_n1h, g_n1h);
    cudaGetSymbolAddress((void**)&p_qh, g_qh);
    cudaGetSymbolAddress((void**)&p_kh, g_kh);
    cudaGetSymbolAddress((void**)&p_vh, g_vh);
    cudaGetSymbolAddress((void**)&p_aoh, g_aoh);
    cudaGetSymbolAddress((void**)&p_h,  g_h);
    cudaGetSymbolAddress((void**)&p_n2h, g_n2h);
    cudaGetSymbolAddress((void**)&p_f1h, g_f1h);
    cudaGetSymbolAddress((void**)&wqkvh, g_wqkvh);
    cudaGetSymbolAddress((void**)&woh, g_woh);
    cudaGetSymbolAddress((void**)&w1h, g_w1h);
    cudaGetSymbolAddress((void**)&w2h, g_w2h);

    const int SMEM1 = 2 * 2 * 16384;   // 64KB

    cudaFuncSetAttribute(fattn_mma,
                         cudaFuncAttributeMaxDynamicSharedMemorySize, ATTN_SMEM);
    cudaFuncSetAttribute(tc_qkv_gemm,
                         cudaFuncAttributeMaxDynamicSharedMemorySize, SMEM1);
    cudaFuncSetAttribute(tc2_gemm<false, true, 0>,
                         cudaFuncAttributeMaxDynamicSharedMemorySize, SMEM1);
    cudaFuncSetAttribute(tc2_gemm<true, false, 1>,
                         cudaFuncAttributeMaxDynamicSharedMemorySize, SMEM1);

    // 0) weight transpose -> fp16
    wsplit4_kernel<<<dim3(DM / 32, DM / 32, 4), 256>>>(
        Wq, Wk, Wv, Wo, wqkvh, woh);
    wsplit_kernel<<<dim3(DFF / 32, DM / 32), 256>>>(W1, w1h, DM, DFF);
    wsplit_kernel<<<dim3(DM / 32, DFF / 32), 256>>>(W2, w2h, DFF, DM);

    // 1) LN1 -> fp16
    ln_kernel<<<NTOK, 256>>>(x, ln1a, ln1b, p_n1h);

    // 2) fused QKV projection (1-term fp16, routed epilogue)
    tc_qkv_gemm<<<dim3(3 * DM / GBN, NTOK / GBM), 256, SMEM1>>>(
        p_n1h, wqkvh, bq, bk, bv, p_qh, p_kh, p_vh);

    // 3) HMMA flash attention (pure fp16 operands; no 1/sqrt(dk) scaling)
    fattn_mma<<<dim3(S_LEN / 128, NHEAD, BATCH), 256, ATTN_SMEM>>>(
        p_qh, p_kh, p_vh, p_aoh);

    // 4) output projection + residual(x) -> h fp32 (1-term)
    dim3 gP(DM / GBN, NTOK / GBM);
    tc2_gemm<false, true, 0><<<gP, 256, SMEM1>>>(
        p_aoh, woh, bo, x, p_h, nullptr, NTOK, DM, DM);

    // 5) LN2 -> fp16
    ln_kernel<<<NTOK, 256>>>(p_h, ln2a, ln2b, p_n2h);

    // 6) FFN up + ReLU -> f1 fp16 (1-term)
    tc2_gemm<true, false, 1><<<dim3(DFF / GBN, NTOK / GBM), 256, SMEM1>>>(
        p_n2h, w1h, b1, nullptr, nullptr, p_f1h, NTOK, DFF, DM);

    // 7) FFN down + residual(h) -> out fp32 (1-term)
    tc2_gemm<false, true, 0><<<dim3(DM / GBN, NTOK / GBM), 256, SMEM1>>>(
        p_f1h, w2h, b2, p_h, out, nullptr, NTOK, DM, DFF);
}